// round 1
// baseline (speedup 1.0000x reference)
#include <cuda_runtime.h>
#include <math.h>

// Problem constants (fixed shapes from reference)
#define BATCH   4
#define SEQ     2048
#define EMBD    1024
#define NHEAD   16
#define HDIM    64
#define MROWS   (BATCH * SEQ)        // 8192
#define QKV_N   (3 * EMBD)           // 3072

// Scratch (device globals: allocation-free per harness rules)
__device__ float g_qkv[(size_t)MROWS * QKV_N];   // [8192, 3072]  q|k|v
__device__ float g_y  [(size_t)MROWS * EMBD];    // [8192, 1024]  attention output

// ---------------------------------------------------------------------------
// SGEMM: C[M,N] = A[M,K] @ B[K,N] + bias[N]
// 128x128 block tile, BK=8, 256 threads, 8x8 microtile, float4 everywhere.
// ---------------------------------------------------------------------------
__global__ __launch_bounds__(256)
void sgemm_bias(const float* __restrict__ A, const float* __restrict__ Bm,
                const float* __restrict__ bias, float* __restrict__ C,
                int M, int N, int K)
{
    __shared__ float As[8][132];   // padded: conflict-free transposed stores
    __shared__ float Bs[8][128];

    const int tid = threadIdx.x;
    const int bm  = blockIdx.y * 128;
    const int bn  = blockIdx.x * 128;
    const int tx  = tid & 15;      // 0..15
    const int ty  = tid >> 4;      // 0..15

    float acc[8][8];
    #pragma unroll
    for (int i = 0; i < 8; i++)
        #pragma unroll
        for (int j = 0; j < 8; j++) acc[i][j] = 0.f;

    const int arow = tid >> 1;          // 0..127
    const int acol = (tid & 1) * 4;     // 0 or 4
    const int brow = tid >> 5;          // 0..7
    const int bcol = (tid & 31) * 4;    // 0..124

    const float* Aptr = A + (size_t)(bm + arow) * K + acol;
    const float* Bptr = Bm + (size_t)brow * N + bn + bcol;

    for (int k0 = 0; k0 < K; k0 += 8) {
        float4 a4 = *(const float4*)(Aptr + k0);
        As[acol + 0][arow] = a4.x;
        As[acol + 1][arow] = a4.y;
        As[acol + 2][arow] = a4.z;
        As[acol + 3][arow] = a4.w;
        *(float4*)&Bs[brow][bcol] = *(const float4*)(Bptr + (size_t)k0 * N);
        __syncthreads();

        #pragma unroll
        for (int k = 0; k < 8; k++) {
            float a[8], b[8];
            *(float4*)&a[0] = *(const float4*)&As[k][ty * 8];
            *(float4*)&a[4] = *(const float4*)&As[k][ty * 8 + 4];
            *(float4*)&b[0] = *(const float4*)&Bs[k][tx * 8];
            *(float4*)&b[4] = *(const float4*)&Bs[k][tx * 8 + 4];
            #pragma unroll
            for (int i = 0; i < 8; i++)
                #pragma unroll
                for (int j = 0; j < 8; j++)
                    acc[i][j] += a[i] * b[j];
        }
        __syncthreads();
    }

    #pragma unroll
    for (int i = 0; i < 8; i++) {
        const int row = bm + ty * 8 + i;
        #pragma unroll
        for (int j = 0; j < 8; j += 4) {
            const int col = bn + tx * 8 + j;
            float4 o;
            o.x = acc[i][j + 0] + bias[col + 0];
            o.y = acc[i][j + 1] + bias[col + 1];
            o.z = acc[i][j + 2] + bias[col + 2];
            o.w = acc[i][j + 3] + bias[col + 3];
            *(float4*)&C[(size_t)row * N + col] = o;
        }
    }
}

// ---------------------------------------------------------------------------
// Flash attention (causal, fp32). Grid: (SEQ/128, B*H). 128 threads,
// one query row per thread. K/V tiles of 64 keys in smem; online softmax
// over 16-key sub-blocks (keeps s[] in registers, bounded code size).
// ---------------------------------------------------------------------------
__global__ __launch_bounds__(128)
void flash_attn(const float* __restrict__ qkv, float* __restrict__ y)
{
    __shared__ float Ks[64][64];
    __shared__ float Vs[64][64];

    const int qt = blockIdx.x;          // query tile 0..15
    const int bh = blockIdx.y;          // 0..63
    const int b  = bh >> 4;
    const int h  = bh & 15;
    const int t  = threadIdx.x;         // 0..127
    const int row = qt * 128 + t;       // query index 0..2047

    // Load this thread's query row into registers
    const size_t qbase = ((size_t)(b * SEQ + row)) * QKV_N + h * HDIM;
    float q[64];
    #pragma unroll
    for (int i = 0; i < 16; i++) {
        float4 v4 = *(const float4*)(qkv + qbase + i * 4);
        q[i*4+0] = v4.x; q[i*4+1] = v4.y; q[i*4+2] = v4.z; q[i*4+3] = v4.w;
    }

    float o[64];
    #pragma unroll
    for (int d = 0; d < 64; d++) o[d] = 0.f;
    float mrow = -1e30f, lrow = 0.f;
    const float scale = 0.125f;  // 1/sqrt(64)

    const int nkt = 2 * qt + 2;  // key tiles needed under causal mask
    for (int kt = 0; kt < nkt; kt++) {
        __syncthreads();
        // Cooperative coalesced load of K and V tiles (64x64 each)
        #pragma unroll
        for (int i = 0; i < 8; i++) {
            const int f  = i * 128 + t;        // float4 index 0..1023
            const int kr = f >> 4;             // key row in tile
            const int c4 = (f & 15) * 4;       // column (float4-aligned)
            const size_t g = ((size_t)(b * SEQ + kt * 64 + kr)) * QKV_N
                           + EMBD + h * HDIM + c4;
            *(float4*)&Ks[kr][c4] = *(const float4*)(qkv + g);
            *(float4*)&Vs[kr][c4] = *(const float4*)(qkv + g + EMBD);
        }
        __syncthreads();

        const bool diag = (kt * 64 + 63 > row);

        #pragma unroll 1
        for (int sub = 0; sub < 4; sub++) {
            float s[16];
            #pragma unroll
            for (int j = 0; j < 16; j++) {
                const int jr = sub * 16 + j;
                float acc = 0.f;
                #pragma unroll
                for (int d4 = 0; d4 < 16; d4++) {
                    float4 k4 = *(const float4*)&Ks[jr][d4 * 4];
                    acc += q[d4*4+0]*k4.x + q[d4*4+1]*k4.y
                         + q[d4*4+2]*k4.z + q[d4*4+3]*k4.w;
                }
                s[j] = acc * scale;
            }
            if (diag) {
                #pragma unroll
                for (int j = 0; j < 16; j++)
                    if (kt * 64 + sub * 16 + j > row) s[j] = -1e30f;
            }
            float tmax = s[0];
            #pragma unroll
            for (int j = 1; j < 16; j++) tmax = fmaxf(tmax, s[j]);
            const float m_new = fmaxf(mrow, tmax);
            const float corr  = __expf(mrow - m_new);
            lrow *= corr;
            #pragma unroll
            for (int d = 0; d < 64; d++) o[d] *= corr;
            mrow = m_new;
            #pragma unroll
            for (int j = 0; j < 16; j++) {
                const float p = __expf(s[j] - m_new);
                lrow += p;
                const int jr = sub * 16 + j;
                #pragma unroll
                for (int d4 = 0; d4 < 16; d4++) {
                    float4 v4 = *(const float4*)&Vs[jr][d4 * 4];
                    o[d4*4+0] += p * v4.x; o[d4*4+1] += p * v4.y;
                    o[d4*4+2] += p * v4.z; o[d4*4+3] += p * v4.w;
                }
            }
        }
    }

    const float inv = 1.f / lrow;
    const size_t ybase = ((size_t)(b * SEQ + row)) * EMBD + h * HDIM;
    #pragma unroll
    for (int i = 0; i < 16; i++) {
        float4 v4;
        v4.x = o[i*4+0] * inv; v4.y = o[i*4+1] * inv;
        v4.z = o[i*4+2] * inv; v4.w = o[i*4+3] * inv;
        *(float4*)&y[ybase + i * 4] = v4;
    }
}

// ---------------------------------------------------------------------------
// Launch
// ---------------------------------------------------------------------------
extern "C" void kernel_launch(void* const* d_in, const int* in_sizes, int n_in,
                              void* d_out, int out_size)
{
    const float* x      = (const float*)d_in[0];  // [4,2048,1024]
    const float* W_attn = (const float*)d_in[1];  // [1024,3072]
    const float* b_attn = (const float*)d_in[2];  // [3072]
    const float* W_proj = (const float*)d_in[3];  // [1024,1024]
    const float* b_proj = (const float*)d_in[4];  // [1024]
    float* out = (float*)d_out;                   // [4,2048,1024]

    float *qkv, *y;
    cudaGetSymbolAddress((void**)&qkv, g_qkv);
    cudaGetSymbolAddress((void**)&y, g_y);

    // 1) QKV projection: [8192,1024] @ [1024,3072] + b -> [8192,3072]
    {
        dim3 grid(QKV_N / 128, MROWS / 128);
        sgemm_bias<<<grid, 256>>>(x, W_attn, b_attn, qkv, MROWS, QKV_N, EMBD);
    }
    // 2) Causal flash attention -> y [8192,1024]
    {
        dim3 grid(SEQ / 128, BATCH * NHEAD);
        flash_attn<<<grid, 128>>>(qkv, y);
    }
    // 3) Output projection: [8192,1024] @ [1024,1024] + b -> out
    {
        dim3 grid(EMBD / 128, MROWS / 128);
        sgemm_bias<<<grid, 256>>>(y, W_proj, b_proj, out, MROWS, EMBD, EMBD);
    }
}

// round 3
// speedup vs baseline: 1.4517x; 1.4517x over previous
#include <cuda_runtime.h>
#include <cuda_bf16.h>
#include <cstdint>
#include <math.h>

// Problem constants
#define BATCH   4
#define SEQ     2048
#define EMBD    1024
#define NHEAD   16
#define HDIM    64
#define MROWS   (BATCH * SEQ)        // 8192
#define QKV_N   (3 * EMBD)           // 3072
#define KP      (3 * EMBD)           // concatenated K' = 3072 (bf16x3 trick)

// ---------------------------------------------------------------------------
// Scratch (device globals: allocation-free per harness rules)
// ---------------------------------------------------------------------------
__device__ float g_qkv[(size_t)MROWS * QKV_N];        // [8192,3072] fp32 q|k|v
__device__ float g_y  [(size_t)MROWS * EMBD];         // [8192,1024] attn out
__device__ __nv_bfloat16 g_a2 [(size_t)MROWS * KP];   // [8192,3072] [Ah|Al|Ah]
__device__ __nv_bfloat16 g_w2a[(size_t)QKV_N * KP];   // [3072,3072] [Wh|Wh|Wl] (W_attn^T)
__device__ __nv_bfloat16 g_w2p[(size_t)EMBD * KP];    // [1024,3072] (W_proj^T)

// ---------------------------------------------------------------------------
// Portable PTX helpers (valid on compute_103: mma.sync / ldmatrix / cp.async)
// ---------------------------------------------------------------------------
__device__ __forceinline__ uint32_t smem_u32(const void* p) {
    uint32_t a;
    asm("{ .reg .u64 t; cvta.to.shared.u64 t, %1; cvt.u32.u64 %0, t; }"
        : "=r"(a) : "l"(p));
    return a;
}

__device__ __forceinline__ void cp_async16(uint32_t dst, const void* src) {
    asm volatile("cp.async.cg.shared.global [%0], [%1], 16;"
                 :: "r"(dst), "l"(src) : "memory");
}
__device__ __forceinline__ void cp_commit() {
    asm volatile("cp.async.commit_group;" ::: "memory");
}
template <int N>
__device__ __forceinline__ void cp_wait() {
    asm volatile("cp.async.wait_group %0;" :: "n"(N) : "memory");
}

__device__ __forceinline__ void ldmatrix_x4(uint32_t* r, uint32_t addr) {
    asm volatile("ldmatrix.sync.aligned.m8n8.x4.shared.b16 {%0,%1,%2,%3}, [%4];"
                 : "=r"(r[0]), "=r"(r[1]), "=r"(r[2]), "=r"(r[3]) : "r"(addr));
}
__device__ __forceinline__ void ldmatrix_x2(uint32_t* r, uint32_t addr) {
    asm volatile("ldmatrix.sync.aligned.m8n8.x2.shared.b16 {%0,%1}, [%2];"
                 : "=r"(r[0]), "=r"(r[1]) : "r"(addr));
}
__device__ __forceinline__ void mma16816(float* c, const uint32_t* a, const uint32_t* b) {
    asm volatile(
        "mma.sync.aligned.m16n8k16.row.col.f32.bf16.bf16.f32 "
        "{%0,%1,%2,%3}, {%4,%5,%6,%7}, {%8,%9}, {%0,%1,%2,%3};"
        : "+f"(c[0]), "+f"(c[1]), "+f"(c[2]), "+f"(c[3])
        : "r"(a[0]), "r"(a[1]), "r"(a[2]), "r"(a[3]), "r"(b[0]), "r"(b[1]));
}

// ---------------------------------------------------------------------------
// Pack x fp32 [rows,1024] -> A2 bf16 [rows,3072] = [hi | lo | hi]
// ---------------------------------------------------------------------------
__global__ __launch_bounds__(256)
void pack_split(const float* __restrict__ src, __nv_bfloat16* __restrict__ dst,
                int n4)   // n4 = rows*1024/4
{
    int i = blockIdx.x * 256 + threadIdx.x;
    if (i >= n4) return;
    const int r  = i >> 8;          // 256 float4 per row
    const int c  = (i & 255) * 4;
    float4 v = ((const float4*)src)[i];
    __nv_bfloat16 h0 = __float2bfloat16(v.x);
    __nv_bfloat16 h1 = __float2bfloat16(v.y);
    __nv_bfloat16 h2 = __float2bfloat16(v.z);
    __nv_bfloat16 h3 = __float2bfloat16(v.w);
    __nv_bfloat162 hp0(h0, h1), hp1(h2, h3);
    __nv_bfloat162 lp0(__float2bfloat16(v.x - __bfloat162float(h0)),
                       __float2bfloat16(v.y - __bfloat162float(h1)));
    __nv_bfloat162 lp1(__float2bfloat16(v.z - __bfloat162float(h2)),
                       __float2bfloat16(v.w - __bfloat162float(h3)));
    __nv_bfloat162* d = (__nv_bfloat162*)(dst + (size_t)r * KP);
    d[(c >> 1) + 0] = hp0;          // hi @ [0,1024)
    d[(c >> 1) + 1] = hp1;
    d[((1024 + c) >> 1) + 0] = lp0; // lo @ [1024,2048)
    d[((1024 + c) >> 1) + 1] = lp1;
    d[((2048 + c) >> 1) + 0] = hp0; // hi @ [2048,3072)
    d[((2048 + c) >> 1) + 1] = hp1;
}

// ---------------------------------------------------------------------------
// W [K=1024, N] fp32 -> W2 [N, 3072] bf16 = per row [hi | hi | lo]
// ---------------------------------------------------------------------------
__global__ __launch_bounds__(256)
void transpose_pack(const float* __restrict__ W, __nv_bfloat16* __restrict__ W2,
                    int Nd)
{
    __shared__ float t[32][33];
    const int n0 = blockIdx.x * 32;
    const int k0 = blockIdx.y * 32;
    const int tx = threadIdx.x & 31;
    const int ty = threadIdx.x >> 5;   // 0..7
    #pragma unroll
    for (int i = 0; i < 32; i += 8)
        t[ty + i][tx] = W[(size_t)(k0 + ty + i) * Nd + n0 + tx];
    __syncthreads();
    #pragma unroll
    for (int i = 0; i < 32; i += 8) {
        float v = t[tx][ty + i];
        __nv_bfloat16 h = __float2bfloat16(v);
        __nv_bfloat16 l = __float2bfloat16(v - __bfloat162float(h));
        __nv_bfloat16* row = W2 + (size_t)(n0 + ty + i) * KP;
        row[k0 + tx]        = h;
        row[1024 + k0 + tx] = h;
        row[2048 + k0 + tx] = l;
    }
}

// ---------------------------------------------------------------------------
// bf16 tensor-core GEMM: C[M,N] = A2[M,KP] @ W2[N,KP]^T + bias
// 128x128 block tile, BK=64, 8 warps (2x4), mma.m16n8k16, cp.async pipeline.
// SMEM tiles [128 rows][128B] with XOR swizzle: group' = group ^ (row & 7).
// ---------------------------------------------------------------------------
#define GEMM_SMEM_SZ 65536   // 2 stages x (A 16KB + B 16KB)

__device__ __forceinline__ void load_stage(uint32_t sA, uint32_t sB,
                                           const __nv_bfloat16* A,
                                           const __nv_bfloat16* B,
                                           int bm, int bn, int kc, int tid)
{
    const size_t ko = (size_t)kc * 64;
    #pragma unroll
    for (int i = 0; i < 4; i++) {
        const int idx = tid + i * 256;      // 0..1023
        const int r = idx >> 3;
        const int g = idx & 7;
        const uint32_t so = (uint32_t)r * 128 + (uint32_t)((g ^ (r & 7)) << 4);
        cp_async16(sA + so, (const char*)(A + (size_t)(bm + r) * KP + ko) + g * 16);
        cp_async16(sB + so, (const char*)(B + (size_t)(bn + r) * KP + ko) + g * 16);
    }
}

__global__ __launch_bounds__(256)
void gemm_bf16(const __nv_bfloat16* __restrict__ A2,
               const __nv_bfloat16* __restrict__ W2,
               const float* __restrict__ bias,
               float* __restrict__ C, int N)
{
    extern __shared__ char dsm[];
    const int tid  = threadIdx.x;
    const int lane = tid & 31;
    const int wid  = tid >> 5;
    const int wm   = wid >> 2;         // 0..1  (64 rows)
    const int wn   = wid & 3;          // 0..3  (32 cols)
    const int bm   = blockIdx.y * 128;
    const int bn   = blockIdx.x * 128;

    const uint32_t sbase = smem_u32(dsm);
    // stage s: A at sbase + s*32768, B at +16384
    float acc[4][4][4];
    #pragma unroll
    for (int mt = 0; mt < 4; mt++)
        #pragma unroll
        for (int nt = 0; nt < 4; nt++)
            #pragma unroll
            for (int j = 0; j < 4; j++) acc[mt][nt][j] = 0.f;

    const int NK = KP / 64;   // 48

    load_stage(sbase, sbase + 16384, A2, W2, bm, bn, 0, tid);
    cp_commit();

    for (int kc = 0; kc < NK; kc++) {
        const int b = kc & 1;
        if (kc + 1 < NK) {
            const uint32_t st = sbase + (b ^ 1) * 32768;
            load_stage(st, st + 16384, A2, W2, bm, bn, kc + 1, tid);
            cp_commit();
            cp_wait<1>();
        } else {
            cp_wait<0>();
        }
        __syncthreads();

        const uint32_t sA = sbase + b * 32768;
        const uint32_t sB = sA + 16384;

        #pragma unroll
        for (int ks = 0; ks < 4; ks++) {
            uint32_t a[4][4], bb[4][2];
            #pragma unroll
            for (int mt = 0; mt < 4; mt++) {
                const int r = wm * 64 + mt * 16 + (lane & 15);
                const int g = ks * 2 + (lane >> 4);
                ldmatrix_x4(a[mt], sA + r * 128 + ((g ^ (r & 7)) << 4));
            }
            #pragma unroll
            for (int nt = 0; nt < 4; nt++) {
                const int n = wn * 32 + nt * 8 + (lane & 7);
                const int g = ks * 2 + ((lane >> 3) & 1);
                ldmatrix_x2(bb[nt], sB + n * 128 + ((g ^ (n & 7)) << 4));
            }
            #pragma unroll
            for (int mt = 0; mt < 4; mt++)
                #pragma unroll
                for (int nt = 0; nt < 4; nt++)
                    mma16816(acc[mt][nt], a[mt], bb[nt]);
        }
        __syncthreads();
    }

    // Epilogue: add bias, store fp32
    #pragma unroll
    for (int mt = 0; mt < 4; mt++) {
        const int r0 = bm + wm * 64 + mt * 16 + (lane >> 2);
        #pragma unroll
        for (int nt = 0; nt < 4; nt++) {
            const int c0 = bn + wn * 32 + nt * 8 + 2 * (lane & 3);
            const float b0 = bias[c0], b1 = bias[c0 + 1];
            float2 v0 = make_float2(acc[mt][nt][0] + b0, acc[mt][nt][1] + b1);
            float2 v1 = make_float2(acc[mt][nt][2] + b0, acc[mt][nt][3] + b1);
            *(float2*)&C[(size_t)r0 * N + c0]       = v0;
            *(float2*)&C[(size_t)(r0 + 8) * N + c0] = v1;
        }
    }
}

// ---------------------------------------------------------------------------
// Flash attention (causal, fp32) — unchanged (known good)
// ---------------------------------------------------------------------------
__global__ __launch_bounds__(128)
void flash_attn(const float* __restrict__ qkv, float* __restrict__ y)
{
    __shared__ float Ks[64][64];
    __shared__ float Vs[64][64];

    const int qt = blockIdx.x;
    const int bh = blockIdx.y;
    const int b  = bh >> 4;
    const int h  = bh & 15;
    const int t  = threadIdx.x;
    const int row = qt * 128 + t;

    const size_t qbase = ((size_t)(b * SEQ + row)) * QKV_N + h * HDIM;
    float q[64];
    #pragma unroll
    for (int i = 0; i < 16; i++) {
        float4 v4 = *(const float4*)(qkv + qbase + i * 4);
        q[i*4+0] = v4.x; q[i*4+1] = v4.y; q[i*4+2] = v4.z; q[i*4+3] = v4.w;
    }

    float o[64];
    #pragma unroll
    for (int d = 0; d < 64; d++) o[d] = 0.f;
    float mrow = -1e30f, lrow = 0.f;
    const float scale = 0.125f;

    const int nkt = 2 * qt + 2;
    for (int kt = 0; kt < nkt; kt++) {
        __syncthreads();
        #pragma unroll
        for (int i = 0; i < 8; i++) {
            const int f  = i * 128 + t;
            const int kr = f >> 4;
            const int c4 = (f & 15) * 4;
            const size_t g = ((size_t)(b * SEQ + kt * 64 + kr)) * QKV_N
                           + EMBD + h * HDIM + c4;
            *(float4*)&Ks[kr][c4] = *(const float4*)(qkv + g);
            *(float4*)&Vs[kr][c4] = *(const float4*)(qkv + g + EMBD);
        }
        __syncthreads();

        const bool diag = (kt * 64 + 63 > row);

        #pragma unroll 1
        for (int sub = 0; sub < 4; sub++) {
            float s[16];
            #pragma unroll
            for (int j = 0; j < 16; j++) {
                const int jr = sub * 16 + j;
                float acc = 0.f;
                #pragma unroll
                for (int d4 = 0; d4 < 16; d4++) {
                    float4 k4 = *(const float4*)&Ks[jr][d4 * 4];
                    acc += q[d4*4+0]*k4.x + q[d4*4+1]*k4.y
                         + q[d4*4+2]*k4.z + q[d4*4+3]*k4.w;
                }
                s[j] = acc * scale;
            }
            if (diag) {
                #pragma unroll
                for (int j = 0; j < 16; j++)
                    if (kt * 64 + sub * 16 + j > row) s[j] = -1e30f;
            }
            float tmax = s[0];
            #pragma unroll
            for (int j = 1; j < 16; j++) tmax = fmaxf(tmax, s[j]);
            const float m_new = fmaxf(mrow, tmax);
            const float corr  = __expf(mrow - m_new);
            lrow *= corr;
            #pragma unroll
            for (int d = 0; d < 64; d++) o[d] *= corr;
            mrow = m_new;
            #pragma unroll
            for (int j = 0; j < 16; j++) {
                const float p = __expf(s[j] - m_new);
                lrow += p;
                const int jr = sub * 16 + j;
                #pragma unroll
                for (int d4 = 0; d4 < 16; d4++) {
                    float4 v4 = *(const float4*)&Vs[jr][d4 * 4];
                    o[d4*4+0] += p * v4.x; o[d4*4+1] += p * v4.y;
                    o[d4*4+2] += p * v4.z; o[d4*4+3] += p * v4.w;
                }
            }
        }
    }

    const float inv = 1.f / lrow;
    const size_t ybase = ((size_t)(b * SEQ + row)) * EMBD + h * HDIM;
    #pragma unroll
    for (int i = 0; i < 16; i++) {
        float4 v4;
        v4.x = o[i*4+0] * inv; v4.y = o[i*4+1] * inv;
        v4.z = o[i*4+2] * inv; v4.w = o[i*4+3] * inv;
        *(float4*)&y[ybase + i * 4] = v4;
    }
}

// ---------------------------------------------------------------------------
// Launch
// ---------------------------------------------------------------------------
extern "C" void kernel_launch(void* const* d_in, const int* in_sizes, int n_in,
                              void* d_out, int out_size)
{
    const float* x      = (const float*)d_in[0];
    const float* W_attn = (const float*)d_in[1];
    const float* b_attn = (const float*)d_in[2];
    const float* W_proj = (const float*)d_in[3];
    const float* b_proj = (const float*)d_in[4];
    float* out = (float*)d_out;

    float *qkv, *y;
    __nv_bfloat16 *a2, *w2a, *w2p;
    cudaGetSymbolAddress((void**)&qkv, g_qkv);
    cudaGetSymbolAddress((void**)&y,   g_y);
    cudaGetSymbolAddress((void**)&a2,  g_a2);
    cudaGetSymbolAddress((void**)&w2a, g_w2a);
    cudaGetSymbolAddress((void**)&w2p, g_w2p);

    cudaFuncSetAttribute(gemm_bf16,
                         cudaFuncAttributeMaxDynamicSharedMemorySize, GEMM_SMEM_SZ);

    const int n4 = MROWS * EMBD / 4;

    // Pack inputs for bf16x3 GEMM
    pack_split<<<(n4 + 255) / 256, 256>>>(x, a2, n4);
    transpose_pack<<<dim3(QKV_N / 32, EMBD / 32), 256>>>(W_attn, w2a, QKV_N);
    transpose_pack<<<dim3(EMBD / 32,  EMBD / 32), 256>>>(W_proj, w2p, EMBD);

    // 1) QKV projection (tensor cores)
    gemm_bf16<<<dim3(QKV_N / 128, MROWS / 128), 256, GEMM_SMEM_SZ>>>(
        a2, w2a, b_attn, qkv, QKV_N);

    // 2) Causal flash attention
    flash_attn<<<dim3(SEQ / 128, BATCH * NHEAD), 128>>>(qkv, y);

    // 3) Output projection (tensor cores)
    pack_split<<<(n4 + 255) / 256, 256>>>(y, a2, n4);
    gemm_bf16<<<dim3(EMBD / 128, MROWS / 128), 256, GEMM_SMEM_SZ>>>(
        a2, w2p, b_proj, out, EMBD);
}

// round 4
// speedup vs baseline: 3.8047x; 2.6209x over previous
#include <cuda_runtime.h>
#include <cuda_bf16.h>
#include <cstdint>
#include <math.h>

// Problem constants
#define BATCH   4
#define SEQ     2048
#define EMBD    1024
#define NHEAD   16
#define HDIM    64
#define MROWS   (BATCH * SEQ)        // 8192
#define QKV_N   (3 * EMBD)           // 3072
#define KP      (3 * EMBD)           // concatenated K' = 3072 (bf16x3 trick)

// ---------------------------------------------------------------------------
// Scratch (device globals: allocation-free per harness rules)
// ---------------------------------------------------------------------------
__device__ float g_qkv[(size_t)MROWS * QKV_N];        // [8192,3072] fp32 q|k|v
__device__ float g_y  [(size_t)MROWS * EMBD];         // [8192,1024] attn out
__device__ __nv_bfloat16 g_a2 [(size_t)MROWS * KP];   // [8192,3072] [Ah|Al|Ah]
__device__ __nv_bfloat16 g_w2a[(size_t)QKV_N * KP];   // [3072,3072] (W_attn^T)
__device__ __nv_bfloat16 g_w2p[(size_t)EMBD * KP];    // [1024,3072] (W_proj^T)
// attention operands, head-major
__device__ __nv_bfloat16 g_Qp[(size_t)BATCH * NHEAD * SEQ * 192]; // [qh|ql|qh]
__device__ __nv_bfloat16 g_Kp[(size_t)BATCH * NHEAD * SEQ * 192]; // [kh|kh|kl]
__device__ __nv_bfloat16 g_Vh[(size_t)BATCH * NHEAD * SEQ * 64];
__device__ __nv_bfloat16 g_Vl[(size_t)BATCH * NHEAD * SEQ * 64];

// ---------------------------------------------------------------------------
// Portable PTX helpers (valid on compute_103)
// ---------------------------------------------------------------------------
__device__ __forceinline__ uint32_t smem_u32(const void* p) {
    uint32_t a;
    asm("{ .reg .u64 t; cvta.to.shared.u64 t, %1; cvt.u32.u64 %0, t; }"
        : "=r"(a) : "l"(p));
    return a;
}
__device__ __forceinline__ void cp_async16(uint32_t dst, const void* src) {
    asm volatile("cp.async.cg.shared.global [%0], [%1], 16;"
                 :: "r"(dst), "l"(src) : "memory");
}
__device__ __forceinline__ void cp_commit() {
    asm volatile("cp.async.commit_group;" ::: "memory");
}
template <int N>
__device__ __forceinline__ void cp_wait() {
    asm volatile("cp.async.wait_group %0;" :: "n"(N) : "memory");
}
__device__ __forceinline__ void ldmatrix_x4(uint32_t* r, uint32_t addr) {
    asm volatile("ldmatrix.sync.aligned.m8n8.x4.shared.b16 {%0,%1,%2,%3}, [%4];"
                 : "=r"(r[0]), "=r"(r[1]), "=r"(r[2]), "=r"(r[3]) : "r"(addr));
}
__device__ __forceinline__ void ldmatrix_x4t(uint32_t* r, uint32_t addr) {
    asm volatile("ldmatrix.sync.aligned.m8n8.x4.trans.shared.b16 {%0,%1,%2,%3}, [%4];"
                 : "=r"(r[0]), "=r"(r[1]), "=r"(r[2]), "=r"(r[3]) : "r"(addr));
}
__device__ __forceinline__ void ldmatrix_x2(uint32_t* r, uint32_t addr) {
    asm volatile("ldmatrix.sync.aligned.m8n8.x2.shared.b16 {%0,%1}, [%2];"
                 : "=r"(r[0]), "=r"(r[1]) : "r"(addr));
}
__device__ __forceinline__ void mma16816(float* c, const uint32_t* a, const uint32_t* b) {
    asm volatile(
        "mma.sync.aligned.m16n8k16.row.col.f32.bf16.bf16.f32 "
        "{%0,%1,%2,%3}, {%4,%5,%6,%7}, {%8,%9}, {%0,%1,%2,%3};"
        : "+f"(c[0]), "+f"(c[1]), "+f"(c[2]), "+f"(c[3])
        : "r"(a[0]), "r"(a[1]), "r"(a[2]), "r"(a[3]), "r"(b[0]), "r"(b[1]));
}
__device__ __forceinline__ float ex2f(float x) {
    float r;
    asm("ex2.approx.f32 %0, %1;" : "=f"(r) : "f"(x));
    return r;
}
__device__ __forceinline__ void split_pack(float x, float y, uint32_t& hi, uint32_t& lo) {
    __nv_bfloat16 hx = __float2bfloat16(x), hy = __float2bfloat16(y);
    __nv_bfloat162 H(hx, hy);
    hi = *reinterpret_cast<uint32_t*>(&H);
    __nv_bfloat162 L(__float2bfloat16(x - __bfloat162float(hx)),
                     __float2bfloat16(y - __bfloat162float(hy)));
    lo = *reinterpret_cast<uint32_t*>(&L);
}

// ---------------------------------------------------------------------------
// Pack x fp32 [rows,1024] -> A2 bf16 [rows,3072] = [hi | lo | hi]
// ---------------------------------------------------------------------------
__global__ __launch_bounds__(256)
void pack_split(const float* __restrict__ src, __nv_bfloat16* __restrict__ dst,
                int n4)
{
    int i = blockIdx.x * 256 + threadIdx.x;
    if (i >= n4) return;
    const int r  = i >> 8;
    const int c  = (i & 255) * 4;
    float4 v = ((const float4*)src)[i];
    __nv_bfloat16 h0 = __float2bfloat16(v.x);
    __nv_bfloat16 h1 = __float2bfloat16(v.y);
    __nv_bfloat16 h2 = __float2bfloat16(v.z);
    __nv_bfloat16 h3 = __float2bfloat16(v.w);
    __nv_bfloat162 hp0(h0, h1), hp1(h2, h3);
    __nv_bfloat162 lp0(__float2bfloat16(v.x - __bfloat162float(h0)),
                       __float2bfloat16(v.y - __bfloat162float(h1)));
    __nv_bfloat162 lp1(__float2bfloat16(v.z - __bfloat162float(h2)),
                       __float2bfloat16(v.w - __bfloat162float(h3)));
    __nv_bfloat162* d = (__nv_bfloat162*)(dst + (size_t)r * KP);
    d[(c >> 1) + 0] = hp0;
    d[(c >> 1) + 1] = hp1;
    d[((1024 + c) >> 1) + 0] = lp0;
    d[((1024 + c) >> 1) + 1] = lp1;
    d[((2048 + c) >> 1) + 0] = hp0;
    d[((2048 + c) >> 1) + 1] = hp1;
}

// ---------------------------------------------------------------------------
// W [K=1024, N] fp32 -> W2 [N, 3072] bf16 = per row [hi | hi | lo]
// ---------------------------------------------------------------------------
__global__ __launch_bounds__(256)
void transpose_pack(const float* __restrict__ W, __nv_bfloat16* __restrict__ W2,
                    int Nd)
{
    __shared__ float t[32][33];
    const int n0 = blockIdx.x * 32;
    const int k0 = blockIdx.y * 32;
    const int tx = threadIdx.x & 31;
    const int ty = threadIdx.x >> 5;
    #pragma unroll
    for (int i = 0; i < 32; i += 8)
        t[ty + i][tx] = W[(size_t)(k0 + ty + i) * Nd + n0 + tx];
    __syncthreads();
    #pragma unroll
    for (int i = 0; i < 32; i += 8) {
        float v = t[tx][ty + i];
        __nv_bfloat16 h = __float2bfloat16(v);
        __nv_bfloat16 l = __float2bfloat16(v - __bfloat162float(h));
        __nv_bfloat16* row = W2 + (size_t)(n0 + ty + i) * KP;
        row[k0 + tx]        = h;
        row[1024 + k0 + tx] = h;
        row[2048 + k0 + tx] = l;
    }
}

// ---------------------------------------------------------------------------
// Pack qkv fp32 [8192,3072] -> head-major attention operands
//   Qp [bh, t, 192] = [qh|ql|qh] ; Kp = [kh|kh|kl] ; Vh/Vl [bh, t, 64]
// ---------------------------------------------------------------------------
__global__ __launch_bounds__(256)
void pack_qkv(const float* __restrict__ qkv,
              __nv_bfloat16* __restrict__ Qp, __nv_bfloat16* __restrict__ Kpp,
              __nv_bfloat16* __restrict__ Vh, __nv_bfloat16* __restrict__ Vl)
{
    const int i = blockIdx.x * 256 + threadIdx.x;   // over MROWS*256
    const int row = i >> 8;
    const int c4  = (i & 255) * 4;
    const int h   = c4 >> 6;
    const int d   = c4 & 63;
    const int b   = row >> 11;
    const int t   = row & 2047;
    const size_t src = (size_t)row * QKV_N;
    float4 q = *(const float4*)(qkv + src + c4);
    float4 k = *(const float4*)(qkv + src + 1024 + c4);
    float4 v = *(const float4*)(qkv + src + 2048 + c4);
    const size_t ob = ((size_t)(b * NHEAD + h) * SEQ + t);

    uint32_t qh0, ql0, qh1, ql1;
    split_pack(q.x, q.y, qh0, ql0);
    split_pack(q.z, q.w, qh1, ql1);
    uint32_t* Qr = (uint32_t*)(Qp + ob * 192);
    Qr[(d >> 1) + 0]   = qh0;  Qr[(d >> 1) + 1]   = qh1;
    Qr[((64 + d) >> 1) + 0] = ql0;  Qr[((64 + d) >> 1) + 1] = ql1;
    Qr[((128 + d) >> 1) + 0] = qh0; Qr[((128 + d) >> 1) + 1] = qh1;

    uint32_t kh0, kl0, kh1, kl1;
    split_pack(k.x, k.y, kh0, kl0);
    split_pack(k.z, k.w, kh1, kl1);
    uint32_t* Kr = (uint32_t*)(Kpp + ob * 192);
    Kr[(d >> 1) + 0]   = kh0;  Kr[(d >> 1) + 1]   = kh1;
    Kr[((64 + d) >> 1) + 0] = kh0;  Kr[((64 + d) >> 1) + 1] = kh1;
    Kr[((128 + d) >> 1) + 0] = kl0; Kr[((128 + d) >> 1) + 1] = kl1;

    uint32_t vh0, vl0, vh1, vl1;
    split_pack(v.x, v.y, vh0, vl0);
    split_pack(v.z, v.w, vh1, vl1);
    uint32_t* VH = (uint32_t*)(Vh + ob * 64);
    uint32_t* VL = (uint32_t*)(Vl + ob * 64);
    VH[(d >> 1) + 0] = vh0;  VH[(d >> 1) + 1] = vh1;
    VL[(d >> 1) + 0] = vl0;  VL[(d >> 1) + 1] = vl1;
}

// ---------------------------------------------------------------------------
// bf16 tensor-core GEMM (unchanged from R3, known good)
// ---------------------------------------------------------------------------
#define GEMM_SMEM_SZ 65536

__device__ __forceinline__ void load_stage(uint32_t sA, uint32_t sB,
                                           const __nv_bfloat16* A,
                                           const __nv_bfloat16* B,
                                           int bm, int bn, int kc, int tid)
{
    const size_t ko = (size_t)kc * 64;
    #pragma unroll
    for (int i = 0; i < 4; i++) {
        const int idx = tid + i * 256;
        const int r = idx >> 3;
        const int g = idx & 7;
        const uint32_t so = (uint32_t)r * 128 + (uint32_t)((g ^ (r & 7)) << 4);
        cp_async16(sA + so, (const char*)(A + (size_t)(bm + r) * KP + ko) + g * 16);
        cp_async16(sB + so, (const char*)(B + (size_t)(bn + r) * KP + ko) + g * 16);
    }
}

__global__ __launch_bounds__(256)
void gemm_bf16(const __nv_bfloat16* __restrict__ A2,
               const __nv_bfloat16* __restrict__ W2,
               const float* __restrict__ bias,
               float* __restrict__ C, int N)
{
    extern __shared__ char dsm[];
    const int tid  = threadIdx.x;
    const int lane = tid & 31;
    const int wid  = tid >> 5;
    const int wm   = wid >> 2;
    const int wn   = wid & 3;
    const int bm   = blockIdx.y * 128;
    const int bn   = blockIdx.x * 128;

    const uint32_t sbase = smem_u32(dsm);
    float acc[4][4][4];
    #pragma unroll
    for (int mt = 0; mt < 4; mt++)
        #pragma unroll
        for (int nt = 0; nt < 4; nt++)
            #pragma unroll
            for (int j = 0; j < 4; j++) acc[mt][nt][j] = 0.f;

    const int NK = KP / 64;

    load_stage(sbase, sbase + 16384, A2, W2, bm, bn, 0, tid);
    cp_commit();

    for (int kc = 0; kc < NK; kc++) {
        const int b = kc & 1;
        if (kc + 1 < NK) {
            const uint32_t st = sbase + (b ^ 1) * 32768;
            load_stage(st, st + 16384, A2, W2, bm, bn, kc + 1, tid);
            cp_commit();
            cp_wait<1>();
        } else {
            cp_wait<0>();
        }
        __syncthreads();

        const uint32_t sA = sbase + b * 32768;
        const uint32_t sB = sA + 16384;

        #pragma unroll
        for (int ks = 0; ks < 4; ks++) {
            uint32_t a[4][4], bb[4][2];
            #pragma unroll
            for (int mt = 0; mt < 4; mt++) {
                const int r = wm * 64 + mt * 16 + (lane & 15);
                const int g = ks * 2 + (lane >> 4);
                ldmatrix_x4(a[mt], sA + r * 128 + ((g ^ (r & 7)) << 4));
            }
            #pragma unroll
            for (int nt = 0; nt < 4; nt++) {
                const int n = wn * 32 + nt * 8 + (lane & 7);
                const int g = ks * 2 + ((lane >> 3) & 1);
                ldmatrix_x2(bb[nt], sB + n * 128 + ((g ^ (n & 7)) << 4));
            }
            #pragma unroll
            for (int mt = 0; mt < 4; mt++)
                #pragma unroll
                for (int nt = 0; nt < 4; nt++)
                    mma16816(acc[mt][nt], a[mt], bb[nt]);
        }
        __syncthreads();
    }

    #pragma unroll
    for (int mt = 0; mt < 4; mt++) {
        const int r0 = bm + wm * 64 + mt * 16 + (lane >> 2);
        #pragma unroll
        for (int nt = 0; nt < 4; nt++) {
            const int c0 = bn + wn * 32 + nt * 8 + 2 * (lane & 3);
            const float b0 = bias[c0], b1 = bias[c0 + 1];
            float2 v0 = make_float2(acc[mt][nt][0] + b0, acc[mt][nt][1] + b1);
            float2 v1 = make_float2(acc[mt][nt][2] + b0, acc[mt][nt][3] + b1);
            *(float2*)&C[(size_t)r0 * N + c0]       = v0;
            *(float2*)&C[(size_t)(r0 + 8) * N + c0] = v1;
        }
    }
}

// ---------------------------------------------------------------------------
// Tensor-core causal flash attention with bf16x3 compensation.
// Block: 128 queries of one (b,h); 8 warps x 16 rows; 64-key tiles.
// SMEM: Q' [128][384B] resident + K' [64][384B] + Vh/Vl [64][128B].
// ---------------------------------------------------------------------------
#define ATT_SMEM (49152 + 24576 + 8192 + 8192)   // 90112
#define CEXP 0.18033688f   // 0.125 * log2(e)

__global__ __launch_bounds__(256, 2)
void flash_attn_tc(const __nv_bfloat16* __restrict__ Qp,
                   const __nv_bfloat16* __restrict__ Kpp,
                   const __nv_bfloat16* __restrict__ Vh,
                   const __nv_bfloat16* __restrict__ Vl,
                   float* __restrict__ y)
{
    extern __shared__ char dsm[];
    const uint32_t sQ  = smem_u32(dsm);
    const uint32_t sK  = sQ + 49152;
    const uint32_t sVh = sK + 24576;
    const uint32_t sVl = sVh + 8192;

    const int qt   = 15 - blockIdx.x;      // heavy tiles first
    const int bh   = blockIdx.y;
    const int b    = bh >> 4;
    const int h    = bh & 15;
    const int tid  = threadIdx.x;
    const int lane = tid & 31;
    const int w    = tid >> 5;
    const int qr0  = qt * 128;

    // ---- load Q' tile (resident) ----
    const __nv_bfloat16* Qg = Qp + ((size_t)bh * SEQ + qr0) * 192;
    #pragma unroll
    for (int i = 0; i < 12; i++) {
        const int idx = tid + i * 256;     // 0..3071
        const int r = idx / 24;
        const int g = idx % 24;
        const uint32_t sw = (g & 24) | ((g ^ r) & 7);
        cp_async16(sQ + r * 384 + sw * 16, Qg + (size_t)r * 192 + g * 8);
    }
    cp_commit();
    cp_wait<0>();
    __syncthreads();

    float O[8][4];
    #pragma unroll
    for (int j = 0; j < 8; j++)
        #pragma unroll
        for (int i = 0; i < 4; i++) O[j][i] = 0.f;
    float m0 = -1e30f, m1 = -1e30f, l0 = 0.f, l1 = 0.f;

    const int wrow = qr0 + w * 16;                 // warp's min row
    const int kt_max_w = (wrow + 15) >> 6;         // last tile this warp needs
    const int nkt = 2 * qt + 2;

    const __nv_bfloat16* Kg  = Kpp + (size_t)bh * SEQ * 192;
    const __nv_bfloat16* VhG = Vh  + (size_t)bh * SEQ * 64;
    const __nv_bfloat16* VlG = Vl  + (size_t)bh * SEQ * 64;

    for (int kt = 0; kt < nkt; kt++) {
        __syncthreads();   // previous tile consumed
        // ---- load K' / Vh / Vl tiles ----
        {
            const __nv_bfloat16* kg = Kg + (size_t)(kt * 64) * 192;
            #pragma unroll
            for (int i = 0; i < 6; i++) {
                const int idx = tid + i * 256;   // 0..1535
                const int r = idx / 24;
                const int g = idx % 24;
                const uint32_t sw = (g & 24) | ((g ^ r) & 7);
                cp_async16(sK + r * 384 + sw * 16, kg + (size_t)r * 192 + g * 8);
            }
            const __nv_bfloat16* vhg = VhG + (size_t)(kt * 64) * 64;
            const __nv_bfloat16* vlg = VlG + (size_t)(kt * 64) * 64;
            #pragma unroll
            for (int i = 0; i < 2; i++) {
                const int idx = tid + i * 256;   // 0..511
                const int r = idx >> 3;
                const int g = idx & 7;
                const uint32_t sw = (uint32_t)((g ^ (r & 7)) << 4);
                cp_async16(sVh + r * 128 + sw, vhg + (size_t)r * 64 + g * 8);
                cp_async16(sVl + r * 128 + sw, vlg + (size_t)r * 64 + g * 8);
            }
        }
        cp_commit();
        cp_wait<0>();
        __syncthreads();

        if (kt > kt_max_w) continue;   // no keys for this warp's rows

        // ---- S = Q'.K'^T (raw scores, fp32) ----
        float S[8][4];
        #pragma unroll
        for (int j = 0; j < 8; j++)
            #pragma unroll
            for (int i = 0; i < 4; i++) S[j][i] = 0.f;

        #pragma unroll
        for (int ks = 0; ks < 12; ks++) {
            uint32_t qf[4];
            {
                const int r = w * 16 + (lane & 15);
                const int g = 2 * ks + (lane >> 4);
                const uint32_t sw = (g & 24) | ((g ^ r) & 7);
                ldmatrix_x4(qf, sQ + r * 384 + sw * 16);
            }
            #pragma unroll
            for (int nt = 0; nt < 8; nt++) {
                uint32_t kb[2];
                const int n = nt * 8 + (lane & 7);
                const int g = 2 * ks + ((lane >> 3) & 1);
                const uint32_t sw = (g & 24) | ((g ^ n) & 7);
                ldmatrix_x2(kb, sK + n * 384 + sw * 16);
                mma16816(S[nt], qf, kb);
            }
        }

        // ---- causal mask (diagonal tiles only) ----
        const int r0g = wrow + (lane >> 2);
        const int r1g = r0g + 8;
        if (kt * 64 + 63 > wrow) {
            #pragma unroll
            for (int nt = 0; nt < 8; nt++) {
                const int c = kt * 64 + nt * 8 + 2 * (lane & 3);
                if (c     > r0g) S[nt][0] = -1e30f;
                if (c + 1 > r0g) S[nt][1] = -1e30f;
                if (c     > r1g) S[nt][2] = -1e30f;
                if (c + 1 > r1g) S[nt][3] = -1e30f;
            }
        }

        // ---- online softmax ----
        float mt0 = -1e30f, mt1 = -1e30f;
        #pragma unroll
        for (int nt = 0; nt < 8; nt++) {
            mt0 = fmaxf(mt0, fmaxf(S[nt][0], S[nt][1]));
            mt1 = fmaxf(mt1, fmaxf(S[nt][2], S[nt][3]));
        }
        mt0 = fmaxf(mt0, __shfl_xor_sync(0xffffffffu, mt0, 1));
        mt0 = fmaxf(mt0, __shfl_xor_sync(0xffffffffu, mt0, 2));
        mt1 = fmaxf(mt1, __shfl_xor_sync(0xffffffffu, mt1, 1));
        mt1 = fmaxf(mt1, __shfl_xor_sync(0xffffffffu, mt1, 2));
        const float mn0 = fmaxf(m0, mt0), mn1 = fmaxf(m1, mt1);
        const float c0 = ex2f((m0 - mn0) * CEXP);
        const float c1 = ex2f((m1 - mn1) * CEXP);
        l0 *= c0; l1 *= c1;
        m0 = mn0; m1 = mn1;
        #pragma unroll
        for (int j = 0; j < 8; j++) {
            O[j][0] *= c0; O[j][1] *= c0;
            O[j][2] *= c1; O[j][3] *= c1;
        }
        #pragma unroll
        for (int nt = 0; nt < 8; nt++) {
            S[nt][0] = ex2f((S[nt][0] - mn0) * CEXP);
            S[nt][1] = ex2f((S[nt][1] - mn0) * CEXP);
            S[nt][2] = ex2f((S[nt][2] - mn1) * CEXP);
            S[nt][3] = ex2f((S[nt][3] - mn1) * CEXP);
            l0 += S[nt][0] + S[nt][1];
            l1 += S[nt][2] + S[nt][3];
        }

        // ---- O += P.V with compensation: ph.vh + pl.vh + ph.vl ----
        #pragma unroll
        for (int ks2 = 0; ks2 < 4; ks2++) {
            uint32_t aph[4], apl[4];
            split_pack(S[2*ks2  ][0], S[2*ks2  ][1], aph[0], apl[0]);
            split_pack(S[2*ks2  ][2], S[2*ks2  ][3], aph[1], apl[1]);
            split_pack(S[2*ks2+1][0], S[2*ks2+1][1], aph[2], apl[2]);
            split_pack(S[2*ks2+1][2], S[2*ks2+1][3], aph[3], apl[3]);
            #pragma unroll
            for (int np = 0; np < 4; np++) {
                const int r = 16 * ks2 + (lane & 15);
                const int g = 2 * np + (lane >> 4);
                const uint32_t sw = (uint32_t)(((g ^ (r & 7)) & 7) << 4)
                                  | (uint32_t)((g & 8) << 4);
                // g ranges 0..7 here (np<4, +1) so (g&8)==0; keep simple:
                const uint32_t addr_off = r * 128 + (((g ^ (r & 7)) & 7) << 4);
                uint32_t bhv[4], blv[4];
                ldmatrix_x4t(bhv, sVh + addr_off);
                mma16816(O[2*np],     aph, bhv + 0);
                mma16816(O[2*np],     apl, bhv + 0);
                mma16816(O[2*np + 1], aph, bhv + 2);
                mma16816(O[2*np + 1], apl, bhv + 2);
                ldmatrix_x4t(blv, sVl + addr_off);
                mma16816(O[2*np],     aph, blv + 0);
                mma16816(O[2*np + 1], aph, blv + 2);
                (void)sw;
            }
        }
    }

    // ---- finalize: reduce l across the 4-lane row group, scale, store ----
    l0 += __shfl_xor_sync(0xffffffffu, l0, 1);
    l0 += __shfl_xor_sync(0xffffffffu, l0, 2);
    l1 += __shfl_xor_sync(0xffffffffu, l1, 1);
    l1 += __shfl_xor_sync(0xffffffffu, l1, 2);
    const float inv0 = 1.f / l0, inv1 = 1.f / l1;
    const int r0g = wrow + (lane >> 2);
    #pragma unroll
    for (int nt = 0; nt < 8; nt++) {
        const int col = h * 64 + nt * 8 + 2 * (lane & 3);
        float2 v0 = make_float2(O[nt][0] * inv0, O[nt][1] * inv0);
        float2 v1 = make_float2(O[nt][2] * inv1, O[nt][3] * inv1);
        *(float2*)&y[(size_t)(b * SEQ + r0g)     * EMBD + col] = v0;
        *(float2*)&y[(size_t)(b * SEQ + r0g + 8) * EMBD + col] = v1;
    }
}

// ---------------------------------------------------------------------------
// Launch
// ---------------------------------------------------------------------------
extern "C" void kernel_launch(void* const* d_in, const int* in_sizes, int n_in,
                              void* d_out, int out_size)
{
    const float* x      = (const float*)d_in[0];
    const float* W_attn = (const float*)d_in[1];
    const float* b_attn = (const float*)d_in[2];
    const float* W_proj = (const float*)d_in[3];
    const float* b_proj = (const float*)d_in[4];
    float* out = (float*)d_out;

    float *qkv, *y;
    __nv_bfloat16 *a2, *w2a, *w2p, *Qp, *Kpq, *Vh, *Vl;
    cudaGetSymbolAddress((void**)&qkv, g_qkv);
    cudaGetSymbolAddress((void**)&y,   g_y);
    cudaGetSymbolAddress((void**)&a2,  g_a2);
    cudaGetSymbolAddress((void**)&w2a, g_w2a);
    cudaGetSymbolAddress((void**)&w2p, g_w2p);
    cudaGetSymbolAddress((void**)&Qp,  g_Qp);
    cudaGetSymbolAddress((void**)&Kpq, g_Kp);
    cudaGetSymbolAddress((void**)&Vh,  g_Vh);
    cudaGetSymbolAddress((void**)&Vl,  g_Vl);

    cudaFuncSetAttribute(gemm_bf16,
                         cudaFuncAttributeMaxDynamicSharedMemorySize, GEMM_SMEM_SZ);
    cudaFuncSetAttribute(flash_attn_tc,
                         cudaFuncAttributeMaxDynamicSharedMemorySize, ATT_SMEM);

    const int n4 = MROWS * EMBD / 4;

    pack_split<<<(n4 + 255) / 256, 256>>>(x, a2, n4);
    transpose_pack<<<dim3(QKV_N / 32, EMBD / 32), 256>>>(W_attn, w2a, QKV_N);
    transpose_pack<<<dim3(EMBD / 32,  EMBD / 32), 256>>>(W_proj, w2p, EMBD);

    // 1) QKV projection (tensor cores)
    gemm_bf16<<<dim3(QKV_N / 128, MROWS / 128), 256, GEMM_SMEM_SZ>>>(
        a2, w2a, b_attn, qkv, QKV_N);

    // 2) pack attention operands + tensor-core flash attention
    pack_qkv<<<MROWS, 256>>>(qkv, Qp, Kpq, Vh, Vl);
    flash_attn_tc<<<dim3(16, BATCH * NHEAD), 256, ATT_SMEM>>>(Qp, Kpq, Vh, Vl, y);

    // 3) output projection (tensor cores)
    pack_split<<<(n4 + 255) / 256, 256>>>(y, a2, n4);
    gemm_bf16<<<dim3(EMBD / 128, MROWS / 128), 256, GEMM_SMEM_SZ>>>(
        a2, w2p, b_proj, out, EMBD);
}

// round 5
// speedup vs baseline: 5.5656x; 1.4628x over previous
#include <cuda_runtime.h>
#include <cuda_fp16.h>
#include <cstdint>
#include <math.h>

// Problem constants
#define BATCH   4
#define SEQ     2048
#define EMBD    1024
#define NHEAD   16
#define HDIM    64
#define MROWS   (BATCH * SEQ)        // 8192
#define QKV_N   (3 * EMBD)           // 3072
#define KP2     2048                 // K' = 2*1024 (fp16 2-term compensation)

// ---------------------------------------------------------------------------
// Scratch (device globals: allocation-free per harness rules)
// ---------------------------------------------------------------------------
__device__ __half g_a2 [(size_t)MROWS * KP2];   // [8192,2048] [hi|lo] (x, then attn-out)
__device__ __half g_w2a[(size_t)QKV_N * KP2];   // [3072,2048] [Wh|Wh] (W_attn^T)
__device__ __half g_w2p[(size_t)EMBD * KP2];    // [1024,2048] (W_proj^T)
// attention operands, head-major
__device__ __half g_Qp[(size_t)BATCH * NHEAD * SEQ * 128]; // [qh|ql]
__device__ __half g_Kp[(size_t)BATCH * NHEAD * SEQ * 128]; // [kh|kh]
__device__ __half g_Vh[(size_t)BATCH * NHEAD * SEQ * 64];
__device__ __half g_Vl[(size_t)BATCH * NHEAD * SEQ * 64];

// ---------------------------------------------------------------------------
// Portable PTX helpers (valid on compute_103)
// ---------------------------------------------------------------------------
__device__ __forceinline__ uint32_t smem_u32(const void* p) {
    uint32_t a;
    asm("{ .reg .u64 t; cvta.to.shared.u64 t, %1; cvt.u32.u64 %0, t; }"
        : "=r"(a) : "l"(p));
    return a;
}
__device__ __forceinline__ void cp_async16(uint32_t dst, const void* src) {
    asm volatile("cp.async.cg.shared.global [%0], [%1], 16;"
                 :: "r"(dst), "l"(src) : "memory");
}
__device__ __forceinline__ void cp_commit() {
    asm volatile("cp.async.commit_group;" ::: "memory");
}
template <int N>
__device__ __forceinline__ void cp_wait() {
    asm volatile("cp.async.wait_group %0;" :: "n"(N) : "memory");
}
__device__ __forceinline__ void ldmatrix_x4(uint32_t* r, uint32_t addr) {
    asm volatile("ldmatrix.sync.aligned.m8n8.x4.shared.b16 {%0,%1,%2,%3}, [%4];"
                 : "=r"(r[0]), "=r"(r[1]), "=r"(r[2]), "=r"(r[3]) : "r"(addr));
}
__device__ __forceinline__ void ldmatrix_x4t(uint32_t* r, uint32_t addr) {
    asm volatile("ldmatrix.sync.aligned.m8n8.x4.trans.shared.b16 {%0,%1,%2,%3}, [%4];"
                 : "=r"(r[0]), "=r"(r[1]), "=r"(r[2]), "=r"(r[3]) : "r"(addr));
}
__device__ __forceinline__ void ldmatrix_x2(uint32_t* r, uint32_t addr) {
    asm volatile("ldmatrix.sync.aligned.m8n8.x2.shared.b16 {%0,%1}, [%2];"
                 : "=r"(r[0]), "=r"(r[1]) : "r"(addr));
}
__device__ __forceinline__ void mma16816h(float* c, const uint32_t* a, const uint32_t* b) {
    asm volatile(
        "mma.sync.aligned.m16n8k16.row.col.f32.f16.f16.f32 "
        "{%0,%1,%2,%3}, {%4,%5,%6,%7}, {%8,%9}, {%0,%1,%2,%3};"
        : "+f"(c[0]), "+f"(c[1]), "+f"(c[2]), "+f"(c[3])
        : "r"(a[0]), "r"(a[1]), "r"(a[2]), "r"(a[3]), "r"(b[0]), "r"(b[1]));
}
__device__ __forceinline__ float ex2f(float x) {
    float r;
    asm("ex2.approx.f32 %0, %1;" : "=f"(r) : "f"(x));
    return r;
}
// split (x,y) into half2 hi + half2 residual
__device__ __forceinline__ void split2h(float x, float y, __half2& H, __half2& L) {
    __half hx = __float2half_rn(x), hy = __float2half_rn(y);
    H = __halves2half2(hx, hy);
    L = __halves2half2(__float2half_rn(x - __half2float(hx)),
                       __float2half_rn(y - __half2float(hy)));
}

// ---------------------------------------------------------------------------
// Pack x fp32 [rows,1024] -> A2 fp16 [rows,2048] = [hi | lo]
// ---------------------------------------------------------------------------
__global__ __launch_bounds__(256)
void pack_split(const float* __restrict__ src, __half* __restrict__ dst, int n4)
{
    int i = blockIdx.x * 256 + threadIdx.x;
    if (i >= n4) return;
    const int r = i >> 8;
    const int c = (i & 255) * 4;
    float4 v = ((const float4*)src)[i];
    __half2 H0, L0, H1, L1;
    split2h(v.x, v.y, H0, L0);
    split2h(v.z, v.w, H1, L1);
    __half2* d = (__half2*)(dst + (size_t)r * KP2);
    d[(c >> 1) + 0] = H0;
    d[(c >> 1) + 1] = H1;
    d[512 + (c >> 1) + 0] = L0;
    d[512 + (c >> 1) + 1] = L1;
}

// ---------------------------------------------------------------------------
// W [K=1024, N] fp32 -> W2 [N, 2048] fp16 = per row [hi | hi]
// ---------------------------------------------------------------------------
__global__ __launch_bounds__(256)
void transpose_pack(const float* __restrict__ W, __half* __restrict__ W2, int Nd)
{
    __shared__ float t[32][33];
    const int n0 = blockIdx.x * 32;
    const int k0 = blockIdx.y * 32;
    const int tx = threadIdx.x & 31;
    const int ty = threadIdx.x >> 5;
    #pragma unroll
    for (int i = 0; i < 32; i += 8)
        t[ty + i][tx] = W[(size_t)(k0 + ty + i) * Nd + n0 + tx];
    __syncthreads();
    #pragma unroll
    for (int i = 0; i < 32; i += 8) {
        float v = t[tx][ty + i];
        __half h = __float2half_rn(v);
        __half* row = W2 + (size_t)(n0 + ty + i) * KP2;
        row[k0 + tx]        = h;
        row[1024 + k0 + tx] = h;
    }
}

// ---------------------------------------------------------------------------
// fp16 tensor-core GEMM: 128x128 tile, BK=64, 8 warps, cp.async double-buffer.
// MODE 0: C = A2.W2^T + bias (fp32 out)
// MODE 1: QKV epilogue — scatter split halves into Qp/Kp/Vh/Vl head-major.
// ---------------------------------------------------------------------------
#define GEMM_SMEM_SZ 65536

__device__ __forceinline__ void load_stage(uint32_t sA, uint32_t sB,
                                           const __half* A, const __half* B,
                                           int bm, int bn, int kc, int tid)
{
    const size_t ko = (size_t)kc * 64;
    #pragma unroll
    for (int i = 0; i < 4; i++) {
        const int idx = tid + i * 256;
        const int r = idx >> 3;
        const int g = idx & 7;
        const uint32_t so = (uint32_t)r * 128 + (uint32_t)((g ^ (r & 7)) << 4);
        cp_async16(sA + so, (const char*)(A + (size_t)(bm + r) * KP2 + ko) + g * 16);
        cp_async16(sB + so, (const char*)(B + (size_t)(bn + r) * KP2 + ko) + g * 16);
    }
}

template <int MODE>
__global__ __launch_bounds__(256)
void gemm_fp16(const __half* __restrict__ A2, const __half* __restrict__ W2,
               const float* __restrict__ bias, float* __restrict__ C, int N,
               __half2* __restrict__ Qp, __half2* __restrict__ Kp,
               __half2* __restrict__ Vh, __half2* __restrict__ Vl)
{
    extern __shared__ char dsm[];
    const int tid  = threadIdx.x;
    const int lane = tid & 31;
    const int wid  = tid >> 5;
    const int wm   = wid >> 2;
    const int wn   = wid & 3;
    const int bm   = blockIdx.y * 128;
    const int bn   = blockIdx.x * 128;

    const uint32_t sbase = smem_u32(dsm);
    float acc[4][4][4];
    #pragma unroll
    for (int mt = 0; mt < 4; mt++)
        #pragma unroll
        for (int nt = 0; nt < 4; nt++)
            #pragma unroll
            for (int j = 0; j < 4; j++) acc[mt][nt][j] = 0.f;

    const int NK = KP2 / 64;   // 32

    load_stage(sbase, sbase + 16384, A2, W2, bm, bn, 0, tid);
    cp_commit();

    for (int kc = 0; kc < NK; kc++) {
        const int b = kc & 1;
        if (kc + 1 < NK) {
            const uint32_t st = sbase + (b ^ 1) * 32768;
            load_stage(st, st + 16384, A2, W2, bm, bn, kc + 1, tid);
            cp_commit();
            cp_wait<1>();
        } else {
            cp_wait<0>();
        }
        __syncthreads();

        const uint32_t sA = sbase + b * 32768;
        const uint32_t sB = sA + 16384;

        #pragma unroll
        for (int ks = 0; ks < 4; ks++) {
            uint32_t a[4][4], bb[4][2];
            #pragma unroll
            for (int mt = 0; mt < 4; mt++) {
                const int r = wm * 64 + mt * 16 + (lane & 15);
                const int g = ks * 2 + (lane >> 4);
                ldmatrix_x4(a[mt], sA + r * 128 + ((g ^ (r & 7)) << 4));
            }
            #pragma unroll
            for (int nt = 0; nt < 4; nt++) {
                const int n = wn * 32 + nt * 8 + (lane & 7);
                const int g = ks * 2 + ((lane >> 3) & 1);
                ldmatrix_x2(bb[nt], sB + n * 128 + ((g ^ (n & 7)) << 4));
            }
            #pragma unroll
            for (int mt = 0; mt < 4; mt++)
                #pragma unroll
                for (int nt = 0; nt < 4; nt++)
                    mma16816h(acc[mt][nt], a[mt], bb[nt]);
        }
        __syncthreads();
    }

    #pragma unroll
    for (int mt = 0; mt < 4; mt++) {
        const int r0 = bm + wm * 64 + mt * 16 + (lane >> 2);
        #pragma unroll
        for (int nt = 0; nt < 4; nt++) {
            const int c0 = bn + wn * 32 + nt * 8 + 2 * (lane & 3);
            const float b0 = bias[c0], b1 = bias[c0 + 1];
            float2 v0 = make_float2(acc[mt][nt][0] + b0, acc[mt][nt][1] + b1);
            float2 v1 = make_float2(acc[mt][nt][2] + b0, acc[mt][nt][3] + b1);
            if (MODE == 0) {
                *(float2*)&C[(size_t)r0 * N + c0]       = v0;
                *(float2*)&C[(size_t)(r0 + 8) * N + c0] = v1;
            } else {
                // scatter to head-major attention operands
                #pragma unroll
                for (int half_row = 0; half_row < 2; half_row++) {
                    const int row = r0 + half_row * 8;
                    const float2 v = half_row ? v1 : v0;
                    const int bb2 = row >> 11;
                    const int t   = row & 2047;
                    const int reg = c0 >> 10;        // 0=q 1=k 2=v
                    const int cc  = c0 & 1023;
                    const int h   = cc >> 6;
                    const int d2  = (cc & 63) >> 1;
                    const size_t ob = ((size_t)(bb2 * NHEAD + h) * SEQ + t);
                    __half2 H, L;
                    split2h(v.x, v.y, H, L);
                    if (reg == 0) {
                        Qp[ob * 64 + d2]      = H;
                        Qp[ob * 64 + 32 + d2] = L;
                    } else if (reg == 1) {
                        Kp[ob * 64 + d2]      = H;
                        Kp[ob * 64 + 32 + d2] = H;
                    } else {
                        Vh[ob * 32 + d2] = H;
                        Vl[ob * 32 + d2] = L;
                    }
                }
            }
        }
    }
}

// ---------------------------------------------------------------------------
// Tensor-core causal flash attention (fp16, 2-term compensation).
// Block: 128 queries of one (b,h); 8 warps x 16 rows; 64-key tiles.
// SMEM: Q' [128][256B] + K' [64][256B] + Vh/Vl [64][128B] = 64KB.
// Epilogue writes packed [Oh|Ol] rows (proj GEMM input) directly.
// ---------------------------------------------------------------------------
#define ATT_SMEM (32768 + 16384 + 8192 + 8192)   // 65536
#define CEXP 0.18033688f   // 0.125 * log2(e)

__global__ __launch_bounds__(256, 2)
void flash_attn_tc(const __half* __restrict__ Qp, const __half* __restrict__ Kpp,
                   const __half* __restrict__ Vh, const __half* __restrict__ Vl,
                   __half* __restrict__ a2out)
{
    extern __shared__ char dsm[];
    const uint32_t sQ  = smem_u32(dsm);
    const uint32_t sK  = sQ + 32768;
    const uint32_t sVh = sK + 16384;
    const uint32_t sVl = sVh + 8192;

    const int qt   = 15 - blockIdx.x;      // heavy tiles first
    const int bh   = blockIdx.y;
    const int b    = bh >> 4;
    const int h    = bh & 15;
    const int tid  = threadIdx.x;
    const int lane = tid & 31;
    const int w    = tid >> 5;
    const int qr0  = qt * 128;

    // ---- load Q' tile (resident): 128 rows x 256B ----
    const __half* Qg = Qp + ((size_t)bh * SEQ + qr0) * 128;
    #pragma unroll
    for (int i = 0; i < 8; i++) {
        const int idx = tid + i * 256;     // 0..2047
        const int r = idx >> 4;
        const int g = idx & 15;
        const uint32_t sw = (g & 8) | ((g ^ r) & 7);
        cp_async16(sQ + r * 256 + sw * 16, Qg + (size_t)r * 128 + g * 8);
    }
    cp_commit();
    cp_wait<0>();
    __syncthreads();

    float O[8][4];
    #pragma unroll
    for (int j = 0; j < 8; j++)
        #pragma unroll
        for (int i = 0; i < 4; i++) O[j][i] = 0.f;
    float m0 = -1e30f, m1 = -1e30f, l0 = 0.f, l1 = 0.f;

    const int wrow = qr0 + w * 16;
    const int kt_max_w = (wrow + 15) >> 6;
    const int nkt = 2 * qt + 2;

    const __half* Kg  = Kpp + (size_t)bh * SEQ * 128;
    const __half* VhG = Vh  + (size_t)bh * SEQ * 64;
    const __half* VlG = Vl  + (size_t)bh * SEQ * 64;

    for (int kt = 0; kt < nkt; kt++) {
        __syncthreads();
        // ---- load K' / Vh / Vl tiles ----
        {
            const __half* kg = Kg + (size_t)(kt * 64) * 128;
            #pragma unroll
            for (int i = 0; i < 4; i++) {
                const int idx = tid + i * 256;   // 0..1023
                const int r = idx >> 4;
                const int g = idx & 15;
                const uint32_t sw = (g & 8) | ((g ^ r) & 7);
                cp_async16(sK + r * 256 + sw * 16, kg + (size_t)r * 128 + g * 8);
            }
            const __half* vhg = VhG + (size_t)(kt * 64) * 64;
            const __half* vlg = VlG + (size_t)(kt * 64) * 64;
            #pragma unroll
            for (int i = 0; i < 2; i++) {
                const int idx = tid + i * 256;   // 0..511
                const int r = idx >> 3;
                const int g = idx & 7;
                const uint32_t sw = (uint32_t)((g ^ (r & 7)) << 4);
                cp_async16(sVh + r * 128 + sw, vhg + (size_t)r * 64 + g * 8);
                cp_async16(sVl + r * 128 + sw, vlg + (size_t)r * 64 + g * 8);
            }
        }
        cp_commit();
        cp_wait<0>();
        __syncthreads();

        if (kt > kt_max_w) continue;

        // ---- S = Q'.K'^T ----
        float S[8][4];
        #pragma unroll
        for (int j = 0; j < 8; j++)
            #pragma unroll
            for (int i = 0; i < 4; i++) S[j][i] = 0.f;

        #pragma unroll
        for (int ks = 0; ks < 8; ks++) {
            uint32_t qf[4];
            {
                const int r = w * 16 + (lane & 15);
                const int g = 2 * ks + (lane >> 4);
                const uint32_t sw = (g & 8) | ((g ^ r) & 7);
                ldmatrix_x4(qf, sQ + r * 256 + sw * 16);
            }
            #pragma unroll
            for (int nt = 0; nt < 8; nt++) {
                uint32_t kb[2];
                const int n = nt * 8 + (lane & 7);
                const int g = 2 * ks + ((lane >> 3) & 1);
                const uint32_t sw = (g & 8) | ((g ^ n) & 7);
                ldmatrix_x2(kb, sK + n * 256 + sw * 16);
                mma16816h(S[nt], qf, kb);
            }
        }

        // ---- causal mask ----
        const int r0g = wrow + (lane >> 2);
        const int r1g = r0g + 8;
        if (kt * 64 + 63 > wrow) {
            #pragma unroll
            for (int nt = 0; nt < 8; nt++) {
                const int c = kt * 64 + nt * 8 + 2 * (lane & 3);
                if (c     > r0g) S[nt][0] = -1e30f;
                if (c + 1 > r0g) S[nt][1] = -1e30f;
                if (c     > r1g) S[nt][2] = -1e30f;
                if (c + 1 > r1g) S[nt][3] = -1e30f;
            }
        }

        // ---- online softmax ----
        float mt0 = -1e30f, mt1 = -1e30f;
        #pragma unroll
        for (int nt = 0; nt < 8; nt++) {
            mt0 = fmaxf(mt0, fmaxf(S[nt][0], S[nt][1]));
            mt1 = fmaxf(mt1, fmaxf(S[nt][2], S[nt][3]));
        }
        mt0 = fmaxf(mt0, __shfl_xor_sync(0xffffffffu, mt0, 1));
        mt0 = fmaxf(mt0, __shfl_xor_sync(0xffffffffu, mt0, 2));
        mt1 = fmaxf(mt1, __shfl_xor_sync(0xffffffffu, mt1, 1));
        mt1 = fmaxf(mt1, __shfl_xor_sync(0xffffffffu, mt1, 2));
        const float mn0 = fmaxf(m0, mt0), mn1 = fmaxf(m1, mt1);
        const float c0 = ex2f((m0 - mn0) * CEXP);
        const float c1 = ex2f((m1 - mn1) * CEXP);
        l0 *= c0; l1 *= c1;
        m0 = mn0; m1 = mn1;
        #pragma unroll
        for (int j = 0; j < 8; j++) {
            O[j][0] *= c0; O[j][1] *= c0;
            O[j][2] *= c1; O[j][3] *= c1;
        }
        #pragma unroll
        for (int nt = 0; nt < 8; nt++) {
            S[nt][0] = ex2f((S[nt][0] - mn0) * CEXP);
            S[nt][1] = ex2f((S[nt][1] - mn0) * CEXP);
            S[nt][2] = ex2f((S[nt][2] - mn1) * CEXP);
            S[nt][3] = ex2f((S[nt][3] - mn1) * CEXP);
            l0 += S[nt][0] + S[nt][1];
            l1 += S[nt][2] + S[nt][3];
        }

        // ---- O += P.(Vh + Vl), P in plain fp16 ----
        #pragma unroll
        for (int ks2 = 0; ks2 < 4; ks2++) {
            uint32_t ap[4];
            __half2 p0 = __floats2half2_rn(S[2*ks2  ][0], S[2*ks2  ][1]);
            __half2 p1 = __floats2half2_rn(S[2*ks2  ][2], S[2*ks2  ][3]);
            __half2 p2 = __floats2half2_rn(S[2*ks2+1][0], S[2*ks2+1][1]);
            __half2 p3 = __floats2half2_rn(S[2*ks2+1][2], S[2*ks2+1][3]);
            ap[0] = *reinterpret_cast<uint32_t*>(&p0);
            ap[1] = *reinterpret_cast<uint32_t*>(&p1);
            ap[2] = *reinterpret_cast<uint32_t*>(&p2);
            ap[3] = *reinterpret_cast<uint32_t*>(&p3);
            #pragma unroll
            for (int np = 0; np < 4; np++) {
                const int r = 16 * ks2 + (lane & 15);
                const int g = 2 * np + (lane >> 4);
                const uint32_t addr_off = r * 128 + (((g ^ (r & 7)) & 7) << 4);
                uint32_t bhv[4], blv[4];
                ldmatrix_x4t(bhv, sVh + addr_off);
                mma16816h(O[2*np],     ap, bhv + 0);
                mma16816h(O[2*np + 1], ap, bhv + 2);
                ldmatrix_x4t(blv, sVl + addr_off);
                mma16816h(O[2*np],     ap, blv + 0);
                mma16816h(O[2*np + 1], ap, blv + 2);
            }
        }
    }

    // ---- finalize: normalize and write packed [Oh|Ol] proj-GEMM input ----
    l0 += __shfl_xor_sync(0xffffffffu, l0, 1);
    l0 += __shfl_xor_sync(0xffffffffu, l0, 2);
    l1 += __shfl_xor_sync(0xffffffffu, l1, 1);
    l1 += __shfl_xor_sync(0xffffffffu, l1, 2);
    const float inv0 = 1.f / l0, inv1 = 1.f / l1;
    const int r0g = wrow + (lane >> 2);
    __half2* a2h = (__half2*)a2out;
    #pragma unroll
    for (int nt = 0; nt < 8; nt++) {
        const int col = h * 64 + nt * 8 + 2 * (lane & 3);
        const size_t row0 = (size_t)(b * SEQ + r0g);
        const size_t row1 = row0 + 8;
        __half2 H, L;
        split2h(O[nt][0] * inv0, O[nt][1] * inv0, H, L);
        a2h[row0 * 1024 + (col >> 1)]       = H;
        a2h[row0 * 1024 + 512 + (col >> 1)] = L;
        split2h(O[nt][2] * inv1, O[nt][3] * inv1, H, L);
        a2h[row1 * 1024 + (col >> 1)]       = H;
        a2h[row1 * 1024 + 512 + (col >> 1)] = L;
    }
}

// ---------------------------------------------------------------------------
// Launch
// ---------------------------------------------------------------------------
extern "C" void kernel_launch(void* const* d_in, const int* in_sizes, int n_in,
                              void* d_out, int out_size)
{
    const float* x      = (const float*)d_in[0];
    const float* W_attn = (const float*)d_in[1];
    const float* b_attn = (const float*)d_in[2];
    const float* W_proj = (const float*)d_in[3];
    const float* b_proj = (const float*)d_in[4];
    float* out = (float*)d_out;

    __half *a2, *w2a, *w2p, *Qp, *Kpq, *Vh, *Vl;
    cudaGetSymbolAddress((void**)&a2,  g_a2);
    cudaGetSymbolAddress((void**)&w2a, g_w2a);
    cudaGetSymbolAddress((void**)&w2p, g_w2p);
    cudaGetSymbolAddress((void**)&Qp,  g_Qp);
    cudaGetSymbolAddress((void**)&Kpq, g_Kp);
    cudaGetSymbolAddress((void**)&Vh,  g_Vh);
    cudaGetSymbolAddress((void**)&Vl,  g_Vl);

    cudaFuncSetAttribute(gemm_fp16<0>,
                         cudaFuncAttributeMaxDynamicSharedMemorySize, GEMM_SMEM_SZ);
    cudaFuncSetAttribute(gemm_fp16<1>,
                         cudaFuncAttributeMaxDynamicSharedMemorySize, GEMM_SMEM_SZ);
    cudaFuncSetAttribute(flash_attn_tc,
                         cudaFuncAttributeMaxDynamicSharedMemorySize, ATT_SMEM);

    const int n4 = MROWS * EMBD / 4;

    // packs
    pack_split<<<(n4 + 255) / 256, 256>>>(x, a2, n4);
    transpose_pack<<<dim3(QKV_N / 32, EMBD / 32), 256>>>(W_attn, w2a, QKV_N);
    transpose_pack<<<dim3(EMBD / 32,  EMBD / 32), 256>>>(W_proj, w2p, EMBD);

    // 1) QKV projection + fused scatter into attention operands
    gemm_fp16<1><<<dim3(QKV_N / 128, MROWS / 128), 256, GEMM_SMEM_SZ>>>(
        a2, w2a, b_attn, nullptr, QKV_N,
        (__half2*)Qp, (__half2*)Kpq, (__half2*)Vh, (__half2*)Vl);

    // 2) tensor-core flash attention, writes packed proj input into a2
    flash_attn_tc<<<dim3(16, BATCH * NHEAD), 256, ATT_SMEM>>>(Qp, Kpq, Vh, Vl, a2);

    // 3) output projection
    gemm_fp16<0><<<dim3(EMBD / 128, MROWS / 128), 256, GEMM_SMEM_SZ>>>(
        a2, w2p, b_proj, out, EMBD, nullptr, nullptr, nullptr, nullptr);
}

// round 6
// speedup vs baseline: 5.6930x; 1.0229x over previous
#include <cuda_runtime.h>
#include <cuda_fp16.h>
#include <cstdint>
#include <math.h>

// Problem constants
#define BATCH   4
#define SEQ     2048
#define EMBD    1024
#define NHEAD   16
#define HDIM    64
#define MROWS   (BATCH * SEQ)        // 8192
#define QKV_N   (3 * EMBD)           // 3072
#define KP2     2048                 // K' = 2*1024 (fp16 2-term compensation)

// ---------------------------------------------------------------------------
// Scratch (device globals: allocation-free per harness rules)
// ---------------------------------------------------------------------------
__device__ __half g_a2 [(size_t)MROWS * KP2];   // [8192,2048] [hi|lo] (x, then attn-out)
__device__ __half g_w2a[(size_t)QKV_N * KP2];   // [3072,2048] [Wh|Wh] (W_attn^T)
__device__ __half g_w2p[(size_t)EMBD * KP2];    // [1024,2048] (W_proj^T)
// attention operands, head-major
__device__ __half g_Qp[(size_t)BATCH * NHEAD * SEQ * 128]; // [qh|ql]
__device__ __half g_Kp[(size_t)BATCH * NHEAD * SEQ * 128]; // [kh|kh]
__device__ __half g_Vh[(size_t)BATCH * NHEAD * SEQ * 64];

// ---------------------------------------------------------------------------
// Portable PTX helpers (valid on compute_103)
// ---------------------------------------------------------------------------
__device__ __forceinline__ uint32_t smem_u32(const void* p) {
    uint32_t a;
    asm("{ .reg .u64 t; cvta.to.shared.u64 t, %1; cvt.u32.u64 %0, t; }"
        : "=r"(a) : "l"(p));
    return a;
}
__device__ __forceinline__ void cp_async16(uint32_t dst, const void* src) {
    asm volatile("cp.async.cg.shared.global [%0], [%1], 16;"
                 :: "r"(dst), "l"(src) : "memory");
}
__device__ __forceinline__ void cp_commit() {
    asm volatile("cp.async.commit_group;" ::: "memory");
}
template <int N>
__device__ __forceinline__ void cp_wait() {
    asm volatile("cp.async.wait_group %0;" :: "n"(N) : "memory");
}
__device__ __forceinline__ void ldmatrix_x4(uint32_t* r, uint32_t addr) {
    asm volatile("ldmatrix.sync.aligned.m8n8.x4.shared.b16 {%0,%1,%2,%3}, [%4];"
                 : "=r"(r[0]), "=r"(r[1]), "=r"(r[2]), "=r"(r[3]) : "r"(addr));
}
__device__ __forceinline__ void ldmatrix_x4t(uint32_t* r, uint32_t addr) {
    asm volatile("ldmatrix.sync.aligned.m8n8.x4.trans.shared.b16 {%0,%1,%2,%3}, [%4];"
                 : "=r"(r[0]), "=r"(r[1]), "=r"(r[2]), "=r"(r[3]) : "r"(addr));
}
__device__ __forceinline__ void ldmatrix_x2(uint32_t* r, uint32_t addr) {
    asm volatile("ldmatrix.sync.aligned.m8n8.x2.shared.b16 {%0,%1}, [%2];"
                 : "=r"(r[0]), "=r"(r[1]) : "r"(addr));
}
__device__ __forceinline__ void mma16816h(float* c, const uint32_t* a, const uint32_t* b) {
    asm volatile(
        "mma.sync.aligned.m16n8k16.row.col.f32.f16.f16.f32 "
        "{%0,%1,%2,%3}, {%4,%5,%6,%7}, {%8,%9}, {%0,%1,%2,%3};"
        : "+f"(c[0]), "+f"(c[1]), "+f"(c[2]), "+f"(c[3])
        : "r"(a[0]), "r"(a[1]), "r"(a[2]), "r"(a[3]), "r"(b[0]), "r"(b[1]));
}
__device__ __forceinline__ float ex2f(float x) {
    float r;
    asm("ex2.approx.f32 %0, %1;" : "=f"(r) : "f"(x));
    return r;
}
// split (x,y) into half2 hi + half2 residual
__device__ __forceinline__ void split2h(float x, float y, __half2& H, __half2& L) {
    __half hx = __float2half_rn(x), hy = __float2half_rn(y);
    H = __halves2half2(hx, hy);
    L = __halves2half2(__float2half_rn(x - __half2float(hx)),
                       __float2half_rn(y - __half2float(hy)));
}

// ---------------------------------------------------------------------------
// Pack x fp32 [rows,1024] -> A2 fp16 [rows,2048] = [hi | lo]
// ---------------------------------------------------------------------------
__global__ __launch_bounds__(256)
void pack_split(const float* __restrict__ src, __half* __restrict__ dst, int n4)
{
    int i = blockIdx.x * 256 + threadIdx.x;
    if (i >= n4) return;
    const int r = i >> 8;
    const int c = (i & 255) * 4;
    float4 v = ((const float4*)src)[i];
    __half2 H0, L0, H1, L1;
    split2h(v.x, v.y, H0, L0);
    split2h(v.z, v.w, H1, L1);
    __half2* d = (__half2*)(dst + (size_t)r * KP2);
    d[(c >> 1) + 0] = H0;
    d[(c >> 1) + 1] = H1;
    d[512 + (c >> 1) + 0] = L0;
    d[512 + (c >> 1) + 1] = L1;
}

// ---------------------------------------------------------------------------
// W [K=1024, N] fp32 -> W2 [N, 2048] fp16 = per row [hi | hi]
// ---------------------------------------------------------------------------
__global__ __launch_bounds__(256)
void transpose_pack(const float* __restrict__ W, __half* __restrict__ W2, int Nd)
{
    __shared__ float t[32][33];
    const int n0 = blockIdx.x * 32;
    const int k0 = blockIdx.y * 32;
    const int tx = threadIdx.x & 31;
    const int ty = threadIdx.x >> 5;
    #pragma unroll
    for (int i = 0; i < 32; i += 8)
        t[ty + i][tx] = W[(size_t)(k0 + ty + i) * Nd + n0 + tx];
    __syncthreads();
    #pragma unroll
    for (int i = 0; i < 32; i += 8) {
        float v = t[tx][ty + i];
        __half h = __float2half_rn(v);
        __half* row = W2 + (size_t)(n0 + ty + i) * KP2;
        row[k0 + tx]        = h;
        row[1024 + k0 + tx] = h;
    }
}

// ---------------------------------------------------------------------------
// fp16 tensor-core GEMM: 128x128 tile, BK=64, 8 warps, cp.async double-buffer.
// MODE 0: C = A2.W2^T + bias (fp32 out)
// MODE 1: QKV epilogue — scatter split halves into Qp/Kp/Vh head-major.
// ---------------------------------------------------------------------------
#define GEMM_SMEM_SZ 65536

__device__ __forceinline__ void load_stage(uint32_t sA, uint32_t sB,
                                           const __half* A, const __half* B,
                                           int bm, int bn, int kc, int tid)
{
    const size_t ko = (size_t)kc * 64;
    #pragma unroll
    for (int i = 0; i < 4; i++) {
        const int idx = tid + i * 256;
        const int r = idx >> 3;
        const int g = idx & 7;
        const uint32_t so = (uint32_t)r * 128 + (uint32_t)((g ^ (r & 7)) << 4);
        cp_async16(sA + so, (const char*)(A + (size_t)(bm + r) * KP2 + ko) + g * 16);
        cp_async16(sB + so, (const char*)(B + (size_t)(bn + r) * KP2 + ko) + g * 16);
    }
}

template <int MODE>
__global__ __launch_bounds__(256, 2)
void gemm_fp16(const __half* __restrict__ A2, const __half* __restrict__ W2,
               const float* __restrict__ bias, float* __restrict__ C, int N,
               __half2* __restrict__ Qp, __half2* __restrict__ Kp,
               __half2* __restrict__ Vh)
{
    extern __shared__ char dsm[];
    const int tid  = threadIdx.x;
    const int lane = tid & 31;
    const int wid  = tid >> 5;
    const int wm   = wid >> 2;
    const int wn   = wid & 3;
    const int bm   = blockIdx.y * 128;
    const int bn   = blockIdx.x * 128;

    const uint32_t sbase = smem_u32(dsm);
    float acc[4][4][4];
    #pragma unroll
    for (int mt = 0; mt < 4; mt++)
        #pragma unroll
        for (int nt = 0; nt < 4; nt++)
            #pragma unroll
            for (int j = 0; j < 4; j++) acc[mt][nt][j] = 0.f;

    const int NK = KP2 / 64;   // 32

    load_stage(sbase, sbase + 16384, A2, W2, bm, bn, 0, tid);
    cp_commit();

    for (int kc = 0; kc < NK; kc++) {
        const int b = kc & 1;
        if (kc + 1 < NK) {
            const uint32_t st = sbase + (b ^ 1) * 32768;
            load_stage(st, st + 16384, A2, W2, bm, bn, kc + 1, tid);
            cp_commit();
            cp_wait<1>();
        } else {
            cp_wait<0>();
        }
        __syncthreads();

        const uint32_t sA = sbase + b * 32768;
        const uint32_t sB = sA + 16384;

        #pragma unroll
        for (int ks = 0; ks < 4; ks++) {
            uint32_t a[4][4], bb[4][2];
            #pragma unroll
            for (int mt = 0; mt < 4; mt++) {
                const int r = wm * 64 + mt * 16 + (lane & 15);
                const int g = ks * 2 + (lane >> 4);
                ldmatrix_x4(a[mt], sA + r * 128 + ((g ^ (r & 7)) << 4));
            }
            #pragma unroll
            for (int nt = 0; nt < 4; nt++) {
                const int n = wn * 32 + nt * 8 + (lane & 7);
                const int g = ks * 2 + ((lane >> 3) & 1);
                ldmatrix_x2(bb[nt], sB + n * 128 + ((g ^ (n & 7)) << 4));
            }
            #pragma unroll
            for (int mt = 0; mt < 4; mt++)
                #pragma unroll
                for (int nt = 0; nt < 4; nt++)
                    mma16816h(acc[mt][nt], a[mt], bb[nt]);
        }
        __syncthreads();
    }

    #pragma unroll
    for (int mt = 0; mt < 4; mt++) {
        const int r0 = bm + wm * 64 + mt * 16 + (lane >> 2);
        #pragma unroll
        for (int nt = 0; nt < 4; nt++) {
            const int c0 = bn + wn * 32 + nt * 8 + 2 * (lane & 3);
            const float b0 = bias[c0], b1 = bias[c0 + 1];
            float2 v0 = make_float2(acc[mt][nt][0] + b0, acc[mt][nt][1] + b1);
            float2 v1 = make_float2(acc[mt][nt][2] + b0, acc[mt][nt][3] + b1);
            if (MODE == 0) {
                *(float2*)&C[(size_t)r0 * N + c0]       = v0;
                *(float2*)&C[(size_t)(r0 + 8) * N + c0] = v1;
            } else {
                // scatter to head-major attention operands
                #pragma unroll
                for (int half_row = 0; half_row < 2; half_row++) {
                    const int row = r0 + half_row * 8;
                    const float2 v = half_row ? v1 : v0;
                    const int bb2 = row >> 11;
                    const int t   = row & 2047;
                    const int reg = c0 >> 10;        // 0=q 1=k 2=v
                    const int cc  = c0 & 1023;
                    const int h   = cc >> 6;
                    const int d2  = (cc & 63) >> 1;
                    const size_t ob = ((size_t)(bb2 * NHEAD + h) * SEQ + t);
                    __half2 H, L;
                    split2h(v.x, v.y, H, L);
                    if (reg == 0) {
                        Qp[ob * 64 + d2]      = H;
                        Qp[ob * 64 + 32 + d2] = L;
                    } else if (reg == 1) {
                        Kp[ob * 64 + d2]      = H;
                        Kp[ob * 64 + 32 + d2] = H;
                    } else {
                        Vh[ob * 32 + d2] = H;
                    }
                }
            }
        }
    }
}

// ---------------------------------------------------------------------------
// Tensor-core causal flash attention (fp16, Q-side compensation only).
// Block: 128 queries of one (b,h); 8 warps x 16 rows; 64-key tiles.
// SMEM: Q' [128][256B] + K' [64][256B] + Vh [64][128B] = 56KB.
// Epilogue writes packed [Oh|Ol] rows (proj GEMM input) directly.
// ---------------------------------------------------------------------------
#define ATT_SMEM (32768 + 16384 + 8192)   // 57344
#define CEXP 0.18033688f   // 0.125 * log2(e)

__global__ __launch_bounds__(256, 2)
void flash_attn_tc(const __half* __restrict__ Qp, const __half* __restrict__ Kpp,
                   const __half* __restrict__ Vh, __half* __restrict__ a2out)
{
    extern __shared__ char dsm[];
    const uint32_t sQ  = smem_u32(dsm);
    const uint32_t sK  = sQ + 32768;
    const uint32_t sVh = sK + 16384;

    const int qt   = 15 - blockIdx.x;      // heavy tiles first
    const int bh   = blockIdx.y;
    const int b    = bh >> 4;
    const int h    = bh & 15;
    const int tid  = threadIdx.x;
    const int lane = tid & 31;
    const int w    = tid >> 5;
    const int qr0  = qt * 128;

    // ---- load Q' tile (resident): 128 rows x 256B ----
    const __half* Qg = Qp + ((size_t)bh * SEQ + qr0) * 128;
    #pragma unroll
    for (int i = 0; i < 8; i++) {
        const int idx = tid + i * 256;     // 0..2047
        const int r = idx >> 4;
        const int g = idx & 15;
        const uint32_t sw = (g & 8) | ((g ^ r) & 7);
        cp_async16(sQ + r * 256 + sw * 16, Qg + (size_t)r * 128 + g * 8);
    }
    cp_commit();
    cp_wait<0>();
    __syncthreads();

    float O[8][4];
    #pragma unroll
    for (int j = 0; j < 8; j++)
        #pragma unroll
        for (int i = 0; i < 4; i++) O[j][i] = 0.f;
    float m0 = -1e30f, m1 = -1e30f, l0 = 0.f, l1 = 0.f;

    const int wrow = qr0 + w * 16;
    const int kt_max_w = (wrow + 15) >> 6;
    const int nkt = 2 * qt + 2;

    const __half* Kg  = Kpp + (size_t)bh * SEQ * 128;
    const __half* VhG = Vh  + (size_t)bh * SEQ * 64;

    for (int kt = 0; kt < nkt; kt++) {
        __syncthreads();
        // ---- load K' / Vh tiles ----
        {
            const __half* kg = Kg + (size_t)(kt * 64) * 128;
            #pragma unroll
            for (int i = 0; i < 4; i++) {
                const int idx = tid + i * 256;   // 0..1023
                const int r = idx >> 4;
                const int g = idx & 15;
                const uint32_t sw = (g & 8) | ((g ^ r) & 7);
                cp_async16(sK + r * 256 + sw * 16, kg + (size_t)r * 128 + g * 8);
            }
            const __half* vhg = VhG + (size_t)(kt * 64) * 64;
            {
                const int idx = tid;             // 0..255, need 512
                #pragma unroll
                for (int i = 0; i < 2; i++) {
                    const int f = idx + i * 256;
                    const int r = f >> 3;
                    const int g = f & 7;
                    const uint32_t sw = (uint32_t)((g ^ (r & 7)) << 4);
                    cp_async16(sVh + r * 128 + sw, vhg + (size_t)r * 64 + g * 8);
                }
            }
        }
        cp_commit();
        cp_wait<0>();
        __syncthreads();

        if (kt > kt_max_w) continue;

        // ---- S = Q'.K'^T ----
        float S[8][4];
        #pragma unroll
        for (int j = 0; j < 8; j++)
            #pragma unroll
            for (int i = 0; i < 4; i++) S[j][i] = 0.f;

        #pragma unroll
        for (int ks = 0; ks < 8; ks++) {
            uint32_t qf[4];
            {
                const int r = w * 16 + (lane & 15);
                const int g = 2 * ks + (lane >> 4);
                const uint32_t sw = (g & 8) | ((g ^ r) & 7);
                ldmatrix_x4(qf, sQ + r * 256 + sw * 16);
            }
            #pragma unroll
            for (int nt = 0; nt < 8; nt++) {
                uint32_t kb[2];
                const int n = nt * 8 + (lane & 7);
                const int g = 2 * ks + ((lane >> 3) & 1);
                const uint32_t sw = (g & 8) | ((g ^ n) & 7);
                ldmatrix_x2(kb, sK + n * 256 + sw * 16);
                mma16816h(S[nt], qf, kb);
            }
        }

        // ---- causal mask ----
        const int r0g = wrow + (lane >> 2);
        const int r1g = r0g + 8;
        if (kt * 64 + 63 > wrow) {
            #pragma unroll
            for (int nt = 0; nt < 8; nt++) {
                const int c = kt * 64 + nt * 8 + 2 * (lane & 3);
                if (c     > r0g) S[nt][0] = -1e30f;
                if (c + 1 > r0g) S[nt][1] = -1e30f;
                if (c     > r1g) S[nt][2] = -1e30f;
                if (c + 1 > r1g) S[nt][3] = -1e30f;
            }
        }

        // ---- online softmax ----
        float mt0 = -1e30f, mt1 = -1e30f;
        #pragma unroll
        for (int nt = 0; nt < 8; nt++) {
            mt0 = fmaxf(mt0, fmaxf(S[nt][0], S[nt][1]));
            mt1 = fmaxf(mt1, fmaxf(S[nt][2], S[nt][3]));
        }
        mt0 = fmaxf(mt0, __shfl_xor_sync(0xffffffffu, mt0, 1));
        mt0 = fmaxf(mt0, __shfl_xor_sync(0xffffffffu, mt0, 2));
        mt1 = fmaxf(mt1, __shfl_xor_sync(0xffffffffu, mt1, 1));
        mt1 = fmaxf(mt1, __shfl_xor_sync(0xffffffffu, mt1, 2));
        const float mn0 = fmaxf(m0, mt0), mn1 = fmaxf(m1, mt1);
        const float c0 = ex2f((m0 - mn0) * CEXP);
        const float c1 = ex2f((m1 - mn1) * CEXP);
        l0 *= c0; l1 *= c1;
        m0 = mn0; m1 = mn1;
        #pragma unroll
        for (int j = 0; j < 8; j++) {
            O[j][0] *= c0; O[j][1] *= c0;
            O[j][2] *= c1; O[j][3] *= c1;
        }
        #pragma unroll
        for (int nt = 0; nt < 8; nt++) {
            S[nt][0] = ex2f((S[nt][0] - mn0) * CEXP);
            S[nt][1] = ex2f((S[nt][1] - mn0) * CEXP);
            S[nt][2] = ex2f((S[nt][2] - mn1) * CEXP);
            S[nt][3] = ex2f((S[nt][3] - mn1) * CEXP);
            l0 += S[nt][0] + S[nt][1];
            l1 += S[nt][2] + S[nt][3];
        }

        // ---- O += P.Vh, P in plain fp16 ----
        #pragma unroll
        for (int ks2 = 0; ks2 < 4; ks2++) {
            uint32_t ap[4];
            __half2 p0 = __floats2half2_rn(S[2*ks2  ][0], S[2*ks2  ][1]);
            __half2 p1 = __floats2half2_rn(S[2*ks2  ][2], S[2*ks2  ][3]);
            __half2 p2 = __floats2half2_rn(S[2*ks2+1][0], S[2*ks2+1][1]);
            __half2 p3 = __floats2half2_rn(S[2*ks2+1][2], S[2*ks2+1][3]);
            ap[0] = *reinterpret_cast<uint32_t*>(&p0);
            ap[1] = *reinterpret_cast<uint32_t*>(&p1);
            ap[2] = *reinterpret_cast<uint32_t*>(&p2);
            ap[3] = *reinterpret_cast<uint32_t*>(&p3);
            #pragma unroll
            for (int np = 0; np < 4; np++) {
                const int r = 16 * ks2 + (lane & 15);
                const int g = 2 * np + (lane >> 4);
                const uint32_t addr_off = r * 128 + (((g ^ (r & 7)) & 7) << 4);
                uint32_t bhv[4];
                ldmatrix_x4t(bhv, sVh + addr_off);
                mma16816h(O[2*np],     ap, bhv + 0);
                mma16816h(O[2*np + 1], ap, bhv + 2);
            }
        }
    }

    // ---- finalize: normalize and write packed [Oh|Ol] proj-GEMM input ----
    l0 += __shfl_xor_sync(0xffffffffu, l0, 1);
    l0 += __shfl_xor_sync(0xffffffffu, l0, 2);
    l1 += __shfl_xor_sync(0xffffffffu, l1, 1);
    l1 += __shfl_xor_sync(0xffffffffu, l1, 2);
    const float inv0 = 1.f / l0, inv1 = 1.f / l1;
    const int r0g = wrow + (lane >> 2);
    __half2* a2h = (__half2*)a2out;
    #pragma unroll
    for (int nt = 0; nt < 8; nt++) {
        const int col = h * 64 + nt * 8 + 2 * (lane & 3);
        const size_t row0 = (size_t)(b * SEQ + r0g);
        const size_t row1 = row0 + 8;
        __half2 H, L;
        split2h(O[nt][0] * inv0, O[nt][1] * inv0, H, L);
        a2h[row0 * 1024 + (col >> 1)]       = H;
        a2h[row0 * 1024 + 512 + (col >> 1)] = L;
        split2h(O[nt][2] * inv1, O[nt][3] * inv1, H, L);
        a2h[row1 * 1024 + (col >> 1)]       = H;
        a2h[row1 * 1024 + 512 + (col >> 1)] = L;
    }
}

// ---------------------------------------------------------------------------
// Launch
// ---------------------------------------------------------------------------
extern "C" void kernel_launch(void* const* d_in, const int* in_sizes, int n_in,
                              void* d_out, int out_size)
{
    const float* x      = (const float*)d_in[0];
    const float* W_attn = (const float*)d_in[1];
    const float* b_attn = (const float*)d_in[2];
    const float* W_proj = (const float*)d_in[3];
    const float* b_proj = (const float*)d_in[4];
    float* out = (float*)d_out;

    __half *a2, *w2a, *w2p, *Qp, *Kpq, *Vh;
    cudaGetSymbolAddress((void**)&a2,  g_a2);
    cudaGetSymbolAddress((void**)&w2a, g_w2a);
    cudaGetSymbolAddress((void**)&w2p, g_w2p);
    cudaGetSymbolAddress((void**)&Qp,  g_Qp);
    cudaGetSymbolAddress((void**)&Kpq, g_Kp);
    cudaGetSymbolAddress((void**)&Vh,  g_Vh);

    cudaFuncSetAttribute(gemm_fp16<0>,
                         cudaFuncAttributeMaxDynamicSharedMemorySize, GEMM_SMEM_SZ);
    cudaFuncSetAttribute(gemm_fp16<1>,
                         cudaFuncAttributeMaxDynamicSharedMemorySize, GEMM_SMEM_SZ);
    cudaFuncSetAttribute(flash_attn_tc,
                         cudaFuncAttributeMaxDynamicSharedMemorySize, ATT_SMEM);

    const int n4 = MROWS * EMBD / 4;

    // packs
    pack_split<<<(n4 + 255) / 256, 256>>>(x, a2, n4);
    transpose_pack<<<dim3(QKV_N / 32, EMBD / 32), 256>>>(W_attn, w2a, QKV_N);
    transpose_pack<<<dim3(EMBD / 32,  EMBD / 32), 256>>>(W_proj, w2p, EMBD);

    // 1) QKV projection + fused scatter into attention operands
    gemm_fp16<1><<<dim3(QKV_N / 128, MROWS / 128), 256, GEMM_SMEM_SZ>>>(
        a2, w2a, b_attn, nullptr, QKV_N,
        (__half2*)Qp, (__half2*)Kpq, (__half2*)Vh);

    // 2) tensor-core flash attention, writes packed proj input into a2
    flash_attn_tc<<<dim3(16, BATCH * NHEAD), 256, ATT_SMEM>>>(Qp, Kpq, Vh, a2);

    // 3) output projection
    gemm_fp16<0><<<dim3(EMBD / 128, MROWS / 128), 256, GEMM_SMEM_SZ>>>(
        a2, w2p, b_proj, out, EMBD, nullptr, nullptr, nullptr);
}

// round 7
// speedup vs baseline: 5.9243x; 1.0406x over previous
#include <cuda_runtime.h>
#include <cuda_fp16.h>
#include <cstdint>
#include <math.h>

// Problem constants
#define BATCH   4
#define SEQ     2048
#define EMBD    1024
#define NHEAD   16
#define HDIM    64
#define MROWS   (BATCH * SEQ)        // 8192
#define QKV_N   (3 * EMBD)           // 3072
#define KP2     2048                 // K' = 2*1024 (fp16 2-term compensation)

// ---------------------------------------------------------------------------
// Scratch (device globals: allocation-free per harness rules)
// ---------------------------------------------------------------------------
__device__ __half g_a2 [(size_t)MROWS * KP2];   // [8192,2048] [hi|lo] (x, then attn-out)
__device__ __half g_w2a[(size_t)QKV_N * KP2];   // [3072,2048] [Wh|Wh] (W_attn^T)
__device__ __half g_w2p[(size_t)EMBD * KP2];    // [1024,2048] (W_proj^T)
// attention operands, head-major
__device__ __half g_Qp[(size_t)BATCH * NHEAD * SEQ * 128]; // [qh|ql]
__device__ __half g_Kp[(size_t)BATCH * NHEAD * SEQ * 128]; // [kh|kh]
__device__ __half g_Vh[(size_t)BATCH * NHEAD * SEQ * 64];

// ---------------------------------------------------------------------------
// Portable PTX helpers (valid on compute_103)
// ---------------------------------------------------------------------------
__device__ __forceinline__ uint32_t smem_u32(const void* p) {
    uint32_t a;
    asm("{ .reg .u64 t; cvta.to.shared.u64 t, %1; cvt.u32.u64 %0, t; }"
        : "=r"(a) : "l"(p));
    return a;
}
__device__ __forceinline__ void cp_async16(uint32_t dst, const void* src) {
    asm volatile("cp.async.cg.shared.global [%0], [%1], 16;"
                 :: "r"(dst), "l"(src) : "memory");
}
__device__ __forceinline__ void cp_commit() {
    asm volatile("cp.async.commit_group;" ::: "memory");
}
template <int N>
__device__ __forceinline__ void cp_wait() {
    asm volatile("cp.async.wait_group %0;" :: "n"(N) : "memory");
}
__device__ __forceinline__ void ldmatrix_x4(uint32_t* r, uint32_t addr) {
    asm volatile("ldmatrix.sync.aligned.m8n8.x4.shared.b16 {%0,%1,%2,%3}, [%4];"
                 : "=r"(r[0]), "=r"(r[1]), "=r"(r[2]), "=r"(r[3]) : "r"(addr));
}
__device__ __forceinline__ void ldmatrix_x4t(uint32_t* r, uint32_t addr) {
    asm volatile("ldmatrix.sync.aligned.m8n8.x4.trans.shared.b16 {%0,%1,%2,%3}, [%4];"
                 : "=r"(r[0]), "=r"(r[1]), "=r"(r[2]), "=r"(r[3]) : "r"(addr));
}
__device__ __forceinline__ void ldmatrix_x2(uint32_t* r, uint32_t addr) {
    asm volatile("ldmatrix.sync.aligned.m8n8.x2.shared.b16 {%0,%1}, [%2];"
                 : "=r"(r[0]), "=r"(r[1]) : "r"(addr));
}
__device__ __forceinline__ void mma16816h(float* c, const uint32_t* a, const uint32_t* b) {
    asm volatile(
        "mma.sync.aligned.m16n8k16.row.col.f32.f16.f16.f32 "
        "{%0,%1,%2,%3}, {%4,%5,%6,%7}, {%8,%9}, {%0,%1,%2,%3};"
        : "+f"(c[0]), "+f"(c[1]), "+f"(c[2]), "+f"(c[3])
        : "r"(a[0]), "r"(a[1]), "r"(a[2]), "r"(a[3]), "r"(b[0]), "r"(b[1]));
}
__device__ __forceinline__ float ex2f(float x) {
    float r;
    asm("ex2.approx.f32 %0, %1;" : "=f"(r) : "f"(x));
    return r;
}
// split (x,y) into half2 hi + half2 residual
__device__ __forceinline__ void split2h(float x, float y, __half2& H, __half2& L) {
    __half hx = __float2half_rn(x), hy = __float2half_rn(y);
    H = __halves2half2(hx, hy);
    L = __halves2half2(__float2half_rn(x - __half2float(hx)),
                       __float2half_rn(y - __half2float(hy)));
}

// ---------------------------------------------------------------------------
// Pack x fp32 [rows,1024] -> A2 fp16 [rows,2048] = [hi | lo]
// ---------------------------------------------------------------------------
__global__ __launch_bounds__(256)
void pack_split(const float* __restrict__ src, __half* __restrict__ dst, int n4)
{
    int i = blockIdx.x * 256 + threadIdx.x;
    if (i >= n4) return;
    const int r = i >> 8;
    const int c = (i & 255) * 4;
    float4 v = ((const float4*)src)[i];
    __half2 H0, L0, H1, L1;
    split2h(v.x, v.y, H0, L0);
    split2h(v.z, v.w, H1, L1);
    __half2* d = (__half2*)(dst + (size_t)r * KP2);
    d[(c >> 1) + 0] = H0;
    d[(c >> 1) + 1] = H1;
    d[512 + (c >> 1) + 0] = L0;
    d[512 + (c >> 1) + 1] = L1;
}

// ---------------------------------------------------------------------------
// W [K=1024, N] fp32 -> W2 [N, 2048] fp16 = per row [hi | hi]
// ---------------------------------------------------------------------------
__global__ __launch_bounds__(256)
void transpose_pack(const float* __restrict__ W, __half* __restrict__ W2, int Nd)
{
    __shared__ float t[32][33];
    const int n0 = blockIdx.x * 32;
    const int k0 = blockIdx.y * 32;
    const int tx = threadIdx.x & 31;
    const int ty = threadIdx.x >> 5;
    #pragma unroll
    for (int i = 0; i < 32; i += 8)
        t[ty + i][tx] = W[(size_t)(k0 + ty + i) * Nd + n0 + tx];
    __syncthreads();
    #pragma unroll
    for (int i = 0; i < 32; i += 8) {
        float v = t[tx][ty + i];
        __half h = __float2half_rn(v);
        __half* row = W2 + (size_t)(n0 + ty + i) * KP2;
        row[k0 + tx]        = h;
        row[1024 + k0 + tx] = h;
    }
}

// ---------------------------------------------------------------------------
// fp16 tensor-core GEMM: 128x128 tile, BK=64, 8 warps, 3-stage cp.async
// pipeline (one __syncthreads per k-chunk). B fragments via ldmatrix.x4.
// MODE 0: C = A2.W2^T + bias (fp32 out)
// MODE 1: QKV epilogue — scatter split halves into Qp/Kp/Vh head-major.
// ---------------------------------------------------------------------------
#define STAGE_SZ     32768               // A 16KB + B 16KB
#define GEMM_SMEM_SZ (3 * STAGE_SZ)      // 98304

__device__ __forceinline__ void load_stage(uint32_t st,
                                           const __half* A, const __half* B,
                                           int bm, int bn, int kc, int tid)
{
    const size_t ko = (size_t)kc * 64;
    const uint32_t sA = st, sB = st + 16384;
    #pragma unroll
    for (int i = 0; i < 4; i++) {
        const int idx = tid + i * 256;
        const int r = idx >> 3;
        const int g = idx & 7;
        const uint32_t so = (uint32_t)r * 128 + (uint32_t)((g ^ (r & 7)) << 4);
        cp_async16(sA + so, (const char*)(A + (size_t)(bm + r) * KP2 + ko) + g * 16);
        cp_async16(sB + so, (const char*)(B + (size_t)(bn + r) * KP2 + ko) + g * 16);
    }
}

template <int MODE>
__global__ __launch_bounds__(256, 2)
void gemm_fp16(const __half* __restrict__ A2, const __half* __restrict__ W2,
               const float* __restrict__ bias, float* __restrict__ C, int N,
               __half2* __restrict__ Qp, __half2* __restrict__ Kp,
               __half2* __restrict__ Vh)
{
    extern __shared__ char dsm[];
    const int tid  = threadIdx.x;
    const int lane = tid & 31;
    const int wid  = tid >> 5;
    const int wm   = wid >> 2;
    const int wn   = wid & 3;
    const int bm   = blockIdx.y * 128;
    const int bn   = blockIdx.x * 128;

    const uint32_t sbase = smem_u32(dsm);
    float acc[4][4][4];
    #pragma unroll
    for (int mt = 0; mt < 4; mt++)
        #pragma unroll
        for (int nt = 0; nt < 4; nt++)
            #pragma unroll
            for (int j = 0; j < 4; j++) acc[mt][nt][j] = 0.f;

    const int NK = KP2 / 64;   // 32

    load_stage(sbase,            A2, W2, bm, bn, 0, tid);
    cp_commit();
    load_stage(sbase + STAGE_SZ, A2, W2, bm, bn, 1, tid);
    cp_commit();

    uint32_t stage = 0;   // buffer index of chunk kc
    for (int kc = 0; kc < NK; kc++) {
        if (kc == NK - 1) cp_wait<0>(); else cp_wait<1>();
        __syncthreads();
        if (kc + 2 < NK) {
            uint32_t nb = stage + 2;
            if (nb >= 3) nb -= 3;
            load_stage(sbase + nb * STAGE_SZ, A2, W2, bm, bn, kc + 2, tid);
            cp_commit();
        }

        const uint32_t sA = sbase + stage * STAGE_SZ;
        const uint32_t sB = sA + 16384;
        if (++stage == 3) stage = 0;

        #pragma unroll
        for (int ks = 0; ks < 4; ks++) {
            uint32_t a[4][4], bb[2][4];
            #pragma unroll
            for (int mt = 0; mt < 4; mt++) {
                const int r = wm * 64 + mt * 16 + (lane & 15);
                const int g = ks * 2 + (lane >> 4);
                ldmatrix_x4(a[mt], sA + r * 128 + ((g ^ (r & 7)) << 4));
            }
            // B: two n-tiles per ldmatrix.x4 -> regs {nt0.b0, nt0.b1, nt1.b0, nt1.b1}
            #pragma unroll
            for (int pp = 0; pp < 2; pp++) {
                const int n = wn * 32 + pp * 16 + ((lane >> 4) << 3) + (lane & 7);
                const int g = ks * 2 + ((lane >> 3) & 1);
                ldmatrix_x4(bb[pp], sB + n * 128 + ((g ^ (n & 7)) << 4));
            }
            #pragma unroll
            for (int mt = 0; mt < 4; mt++) {
                mma16816h(acc[mt][0], a[mt], bb[0] + 0);
                mma16816h(acc[mt][1], a[mt], bb[0] + 2);
                mma16816h(acc[mt][2], a[mt], bb[1] + 0);
                mma16816h(acc[mt][3], a[mt], bb[1] + 2);
            }
        }
    }
    __syncthreads();

    #pragma unroll
    for (int mt = 0; mt < 4; mt++) {
        const int r0 = bm + wm * 64 + mt * 16 + (lane >> 2);
        #pragma unroll
        for (int nt = 0; nt < 4; nt++) {
            const int c0 = bn + wn * 32 + nt * 8 + 2 * (lane & 3);
            const float b0 = bias[c0], b1 = bias[c0 + 1];
            float2 v0 = make_float2(acc[mt][nt][0] + b0, acc[mt][nt][1] + b1);
            float2 v1 = make_float2(acc[mt][nt][2] + b0, acc[mt][nt][3] + b1);
            if (MODE == 0) {
                *(float2*)&C[(size_t)r0 * N + c0]       = v0;
                *(float2*)&C[(size_t)(r0 + 8) * N + c0] = v1;
            } else {
                // scatter to head-major attention operands
                #pragma unroll
                for (int half_row = 0; half_row < 2; half_row++) {
                    const int row = r0 + half_row * 8;
                    const float2 v = half_row ? v1 : v0;
                    const int bb2 = row >> 11;
                    const int t   = row & 2047;
                    const int reg = c0 >> 10;        // 0=q 1=k 2=v
                    const int cc  = c0 & 1023;
                    const int h   = cc >> 6;
                    const int d2  = (cc & 63) >> 1;
                    const size_t ob = ((size_t)(bb2 * NHEAD + h) * SEQ + t);
                    __half2 H, L;
                    split2h(v.x, v.y, H, L);
                    if (reg == 0) {
                        Qp[ob * 64 + d2]      = H;
                        Qp[ob * 64 + 32 + d2] = L;
                    } else if (reg == 1) {
                        Kp[ob * 64 + d2]      = H;
                        Kp[ob * 64 + 32 + d2] = H;
                    } else {
                        Vh[ob * 32 + d2] = H;
                    }
                }
            }
        }
    }
}

// ---------------------------------------------------------------------------
// Tensor-core causal flash attention (fp16, Q-side compensation only).
// Block: 128 queries of one (b,h); 8 warps x 16 rows; 64-key tiles.
// SMEM: Q' [128][256B] + K' [64][256B] + Vh [64][128B] = 56KB.
// Epilogue writes packed [Oh|Ol] rows (proj GEMM input) directly.
// ---------------------------------------------------------------------------
#define ATT_SMEM (32768 + 16384 + 8192)   // 57344
#define CEXP 0.18033688f   // 0.125 * log2(e)

__global__ __launch_bounds__(256, 2)
void flash_attn_tc(const __half* __restrict__ Qp, const __half* __restrict__ Kpp,
                   const __half* __restrict__ Vh, __half* __restrict__ a2out)
{
    extern __shared__ char dsm[];
    const uint32_t sQ  = smem_u32(dsm);
    const uint32_t sK  = sQ + 32768;
    const uint32_t sVh = sK + 16384;

    const int qt   = 15 - blockIdx.x;      // heavy tiles first
    const int bh   = blockIdx.y;
    const int b    = bh >> 4;
    const int h    = bh & 15;
    const int tid  = threadIdx.x;
    const int lane = tid & 31;
    const int w    = tid >> 5;
    const int qr0  = qt * 128;

    // ---- load Q' tile (resident): 128 rows x 256B ----
    const __half* Qg = Qp + ((size_t)bh * SEQ + qr0) * 128;
    #pragma unroll
    for (int i = 0; i < 8; i++) {
        const int idx = tid + i * 256;     // 0..2047
        const int r = idx >> 4;
        const int g = idx & 15;
        const uint32_t sw = (g & 8) | ((g ^ r) & 7);
        cp_async16(sQ + r * 256 + sw * 16, Qg + (size_t)r * 128 + g * 8);
    }
    cp_commit();
    cp_wait<0>();
    __syncthreads();

    float O[8][4];
    #pragma unroll
    for (int j = 0; j < 8; j++)
        #pragma unroll
        for (int i = 0; i < 4; i++) O[j][i] = 0.f;
    float m0 = -1e30f, m1 = -1e30f, l0 = 0.f, l1 = 0.f;

    const int wrow = qr0 + w * 16;
    const int kt_max_w = (wrow + 15) >> 6;
    const int nkt = 2 * qt + 2;

    const __half* Kg  = Kpp + (size_t)bh * SEQ * 128;
    const __half* VhG = Vh  + (size_t)bh * SEQ * 64;

    for (int kt = 0; kt < nkt; kt++) {
        __syncthreads();
        // ---- load K' / Vh tiles ----
        {
            const __half* kg = Kg + (size_t)(kt * 64) * 128;
            #pragma unroll
            for (int i = 0; i < 4; i++) {
                const int idx = tid + i * 256;   // 0..1023
                const int r = idx >> 4;
                const int g = idx & 15;
                const uint32_t sw = (g & 8) | ((g ^ r) & 7);
                cp_async16(sK + r * 256 + sw * 16, kg + (size_t)r * 128 + g * 8);
            }
            const __half* vhg = VhG + (size_t)(kt * 64) * 64;
            #pragma unroll
            for (int i = 0; i < 2; i++) {
                const int f = tid + i * 256;
                const int r = f >> 3;
                const int g = f & 7;
                const uint32_t sw = (uint32_t)((g ^ (r & 7)) << 4);
                cp_async16(sVh + r * 128 + sw, vhg + (size_t)r * 64 + g * 8);
            }
        }
        cp_commit();
        cp_wait<0>();
        __syncthreads();

        if (kt > kt_max_w) continue;

        // ---- S = Q'.K'^T ----
        float S[8][4];
        #pragma unroll
        for (int j = 0; j < 8; j++)
            #pragma unroll
            for (int i = 0; i < 4; i++) S[j][i] = 0.f;

        #pragma unroll
        for (int ks = 0; ks < 8; ks++) {
            uint32_t qf[4];
            {
                const int r = w * 16 + (lane & 15);
                const int g = 2 * ks + (lane >> 4);
                const uint32_t sw = (g & 8) | ((g ^ r) & 7);
                ldmatrix_x4(qf, sQ + r * 256 + sw * 16);
            }
            #pragma unroll
            for (int nt = 0; nt < 8; nt++) {
                uint32_t kb[2];
                const int n = nt * 8 + (lane & 7);
                const int g = 2 * ks + ((lane >> 3) & 1);
                const uint32_t sw = (g & 8) | ((g ^ n) & 7);
                ldmatrix_x2(kb, sK + n * 256 + sw * 16);
                mma16816h(S[nt], qf, kb);
            }
        }

        // ---- causal mask ----
        const int r0g = wrow + (lane >> 2);
        const int r1g = r0g + 8;
        if (kt * 64 + 63 > wrow) {
            #pragma unroll
            for (int nt = 0; nt < 8; nt++) {
                const int c = kt * 64 + nt * 8 + 2 * (lane & 3);
                if (c     > r0g) S[nt][0] = -1e30f;
                if (c + 1 > r0g) S[nt][1] = -1e30f;
                if (c     > r1g) S[nt][2] = -1e30f;
                if (c + 1 > r1g) S[nt][3] = -1e30f;
            }
        }

        // ---- online softmax ----
        float mt0 = -1e30f, mt1 = -1e30f;
        #pragma unroll
        for (int nt = 0; nt < 8; nt++) {
            mt0 = fmaxf(mt0, fmaxf(S[nt][0], S[nt][1]));
            mt1 = fmaxf(mt1, fmaxf(S[nt][2], S[nt][3]));
        }
        mt0 = fmaxf(mt0, __shfl_xor_sync(0xffffffffu, mt0, 1));
        mt0 = fmaxf(mt0, __shfl_xor_sync(0xffffffffu, mt0, 2));
        mt1 = fmaxf(mt1, __shfl_xor_sync(0xffffffffu, mt1, 1));
        mt1 = fmaxf(mt1, __shfl_xor_sync(0xffffffffu, mt1, 2));
        const float mn0 = fmaxf(m0, mt0), mn1 = fmaxf(m1, mt1);
        const float c0 = ex2f((m0 - mn0) * CEXP);
        const float c1 = ex2f((m1 - mn1) * CEXP);
        l0 *= c0; l1 *= c1;
        m0 = mn0; m1 = mn1;
        #pragma unroll
        for (int j = 0; j < 8; j++) {
            O[j][0] *= c0; O[j][1] *= c0;
            O[j][2] *= c1; O[j][3] *= c1;
        }
        #pragma unroll
        for (int nt = 0; nt < 8; nt++) {
            S[nt][0] = ex2f((S[nt][0] - mn0) * CEXP);
            S[nt][1] = ex2f((S[nt][1] - mn0) * CEXP);
            S[nt][2] = ex2f((S[nt][2] - mn1) * CEXP);
            S[nt][3] = ex2f((S[nt][3] - mn1) * CEXP);
            l0 += S[nt][0] + S[nt][1];
            l1 += S[nt][2] + S[nt][3];
        }

        // ---- O += P.Vh, P in plain fp16 ----
        #pragma unroll
        for (int ks2 = 0; ks2 < 4; ks2++) {
            uint32_t ap[4];
            __half2 p0 = __floats2half2_rn(S[2*ks2  ][0], S[2*ks2  ][1]);
            __half2 p1 = __floats2half2_rn(S[2*ks2  ][2], S[2*ks2  ][3]);
            __half2 p2 = __floats2half2_rn(S[2*ks2+1][0], S[2*ks2+1][1]);
            __half2 p3 = __floats2half2_rn(S[2*ks2+1][2], S[2*ks2+1][3]);
            ap[0] = *reinterpret_cast<uint32_t*>(&p0);
            ap[1] = *reinterpret_cast<uint32_t*>(&p1);
            ap[2] = *reinterpret_cast<uint32_t*>(&p2);
            ap[3] = *reinterpret_cast<uint32_t*>(&p3);
            #pragma unroll
            for (int np = 0; np < 4; np++) {
                const int r = 16 * ks2 + (lane & 15);
                const int g = 2 * np + (lane >> 4);
                const uint32_t addr_off = r * 128 + (((g ^ (r & 7)) & 7) << 4);
                uint32_t bhv[4];
                ldmatrix_x4t(bhv, sVh + addr_off);
                mma16816h(O[2*np],     ap, bhv + 0);
                mma16816h(O[2*np + 1], ap, bhv + 2);
            }
        }
    }

    // ---- finalize: normalize and write packed [Oh|Ol] proj-GEMM input ----
    l0 += __shfl_xor_sync(0xffffffffu, l0, 1);
    l0 += __shfl_xor_sync(0xffffffffu, l0, 2);
    l1 += __shfl_xor_sync(0xffffffffu, l1, 1);
    l1 += __shfl_xor_sync(0xffffffffu, l1, 2);
    const float inv0 = 1.f / l0, inv1 = 1.f / l1;
    const int r0g = wrow + (lane >> 2);
    __half2* a2h = (__half2*)a2out;
    #pragma unroll
    for (int nt = 0; nt < 8; nt++) {
        const int col = h * 64 + nt * 8 + 2 * (lane & 3);
        const size_t row0 = (size_t)(b * SEQ + r0g);
        const size_t row1 = row0 + 8;
        __half2 H, L;
        split2h(O[nt][0] * inv0, O[nt][1] * inv0, H, L);
        a2h[row0 * 1024 + (col >> 1)]       = H;
        a2h[row0 * 1024 + 512 + (col >> 1)] = L;
        split2h(O[nt][2] * inv1, O[nt][3] * inv1, H, L);
        a2h[row1 * 1024 + (col >> 1)]       = H;
        a2h[row1 * 1024 + 512 + (col >> 1)] = L;
    }
}

// ---------------------------------------------------------------------------
// Launch
// ---------------------------------------------------------------------------
extern "C" void kernel_launch(void* const* d_in, const int* in_sizes, int n_in,
                              void* d_out, int out_size)
{
    const float* x      = (const float*)d_in[0];
    const float* W_attn = (const float*)d_in[1];
    const float* b_attn = (const float*)d_in[2];
    const float* W_proj = (const float*)d_in[3];
    const float* b_proj = (const float*)d_in[4];
    float* out = (float*)d_out;

    __half *a2, *w2a, *w2p, *Qp, *Kpq, *Vh;
    cudaGetSymbolAddress((void**)&a2,  g_a2);
    cudaGetSymbolAddress((void**)&w2a, g_w2a);
    cudaGetSymbolAddress((void**)&w2p, g_w2p);
    cudaGetSymbolAddress((void**)&Qp,  g_Qp);
    cudaGetSymbolAddress((void**)&Kpq, g_Kp);
    cudaGetSymbolAddress((void**)&Vh,  g_Vh);

    cudaFuncSetAttribute(gemm_fp16<0>,
                         cudaFuncAttributeMaxDynamicSharedMemorySize, GEMM_SMEM_SZ);
    cudaFuncSetAttribute(gemm_fp16<1>,
                         cudaFuncAttributeMaxDynamicSharedMemorySize, GEMM_SMEM_SZ);
    cudaFuncSetAttribute(flash_attn_tc,
                         cudaFuncAttributeMaxDynamicSharedMemorySize, ATT_SMEM);

    const int n4 = MROWS * EMBD / 4;

    // packs
    pack_split<<<(n4 + 255) / 256, 256>>>(x, a2, n4);
    transpose_pack<<<dim3(QKV_N / 32, EMBD / 32), 256>>>(W_attn, w2a, QKV_N);
    transpose_pack<<<dim3(EMBD / 32,  EMBD / 32), 256>>>(W_proj, w2p, EMBD);

    // 1) QKV projection + fused scatter into attention operands
    gemm_fp16<1><<<dim3(QKV_N / 128, MROWS / 128), 256, GEMM_SMEM_SZ>>>(
        a2, w2a, b_attn, nullptr, QKV_N,
        (__half2*)Qp, (__half2*)Kpq, (__half2*)Vh);

    // 2) tensor-core flash attention, writes packed proj input into a2
    flash_attn_tc<<<dim3(16, BATCH * NHEAD), 256, ATT_SMEM>>>(Qp, Kpq, Vh, a2);

    // 3) output projection
    gemm_fp16<0><<<dim3(EMBD / 128, MROWS / 128), 256, GEMM_SMEM_SZ>>>(
        a2, w2p, b_proj, out, EMBD, nullptr, nullptr, nullptr);
}

// round 8
// speedup vs baseline: 8.5858x; 1.4493x over previous
#include <cuda_runtime.h>
#include <cuda_fp16.h>
#include <cstdint>
#include <math.h>

// Problem constants
#define BATCH   4
#define SEQ     2048
#define EMBD    1024
#define NHEAD   16
#define HDIM    64
#define MROWS   (BATCH * SEQ)        // 8192
#define QKV_N   (3 * EMBD)           // 3072

// ---------------------------------------------------------------------------
// Scratch (device globals: allocation-free per harness rules)
// ---------------------------------------------------------------------------
__device__ __half g_a2 [(size_t)MROWS * EMBD];  // [8192,1024] fp16 (x, then attn-out)
__device__ __half g_w2a[(size_t)QKV_N * EMBD];  // [3072,1024] fp16 W_attn^T
__device__ __half g_w2p[(size_t)EMBD * EMBD];   // [1024,1024] fp16 W_proj^T
// attention operands, head-major
__device__ __half g_Qp[(size_t)BATCH * NHEAD * SEQ * 128]; // [qh|ql] (comp kept)
__device__ __half g_Kp[(size_t)BATCH * NHEAD * SEQ * 64];  // kh
__device__ __half g_Vh[(size_t)BATCH * NHEAD * SEQ * 64];  // vh

// ---------------------------------------------------------------------------
// Portable PTX helpers (valid on compute_103)
// ---------------------------------------------------------------------------
__device__ __forceinline__ uint32_t smem_u32(const void* p) {
    uint32_t a;
    asm("{ .reg .u64 t; cvta.to.shared.u64 t, %1; cvt.u32.u64 %0, t; }"
        : "=r"(a) : "l"(p));
    return a;
}
__device__ __forceinline__ void cp_async16(uint32_t dst, const void* src) {
    asm volatile("cp.async.cg.shared.global [%0], [%1], 16;"
                 :: "r"(dst), "l"(src) : "memory");
}
__device__ __forceinline__ void cp_commit() {
    asm volatile("cp.async.commit_group;" ::: "memory");
}
template <int N>
__device__ __forceinline__ void cp_wait() {
    asm volatile("cp.async.wait_group %0;" :: "n"(N) : "memory");
}
__device__ __forceinline__ void ldmatrix_x4(uint32_t* r, uint32_t addr) {
    asm volatile("ldmatrix.sync.aligned.m8n8.x4.shared.b16 {%0,%1,%2,%3}, [%4];"
                 : "=r"(r[0]), "=r"(r[1]), "=r"(r[2]), "=r"(r[3]) : "r"(addr));
}
__device__ __forceinline__ void ldmatrix_x4t(uint32_t* r, uint32_t addr) {
    asm volatile("ldmatrix.sync.aligned.m8n8.x4.trans.shared.b16 {%0,%1,%2,%3}, [%4];"
                 : "=r"(r[0]), "=r"(r[1]), "=r"(r[2]), "=r"(r[3]) : "r"(addr));
}
__device__ __forceinline__ void ldmatrix_x2(uint32_t* r, uint32_t addr) {
    asm volatile("ldmatrix.sync.aligned.m8n8.x2.shared.b16 {%0,%1}, [%2];"
                 : "=r"(r[0]), "=r"(r[1]) : "r"(addr));
}
__device__ __forceinline__ void mma16816h(float* c, const uint32_t* a, const uint32_t* b) {
    asm volatile(
        "mma.sync.aligned.m16n8k16.row.col.f32.f16.f16.f32 "
        "{%0,%1,%2,%3}, {%4,%5,%6,%7}, {%8,%9}, {%0,%1,%2,%3};"
        : "+f"(c[0]), "+f"(c[1]), "+f"(c[2]), "+f"(c[3])
        : "r"(a[0]), "r"(a[1]), "r"(a[2]), "r"(a[3]), "r"(b[0]), "r"(b[1]));
}
__device__ __forceinline__ float ex2f(float x) {
    float r;
    asm("ex2.approx.f32 %0, %1;" : "=f"(r) : "f"(x));
    return r;
}
// split (x,y) into half2 hi + half2 residual
__device__ __forceinline__ void split2h(float x, float y, __half2& H, __half2& L) {
    __half hx = __float2half_rn(x), hy = __float2half_rn(y);
    H = __halves2half2(hx, hy);
    L = __halves2half2(__float2half_rn(x - __half2float(hx)),
                       __float2half_rn(y - __half2float(hy)));
}

// ---------------------------------------------------------------------------
// Pack x fp32 [rows,1024] -> fp16 [rows,1024]
// ---------------------------------------------------------------------------
__global__ __launch_bounds__(256)
void pack_half(const float* __restrict__ src, __half* __restrict__ dst, int n4)
{
    int i = blockIdx.x * 256 + threadIdx.x;
    if (i >= n4) return;
    float4 v = ((const float4*)src)[i];
    __half2* d = (__half2*)dst;
    d[2 * i + 0] = __floats2half2_rn(v.x, v.y);
    d[2 * i + 1] = __floats2half2_rn(v.z, v.w);
}

// ---------------------------------------------------------------------------
// W [K=1024, N] fp32 -> W2 [N, 1024] fp16
// ---------------------------------------------------------------------------
__global__ __launch_bounds__(256)
void transpose_pack(const float* __restrict__ W, __half* __restrict__ W2, int Nd)
{
    __shared__ float t[32][33];
    const int n0 = blockIdx.x * 32;
    const int k0 = blockIdx.y * 32;
    const int tx = threadIdx.x & 31;
    const int ty = threadIdx.x >> 5;
    #pragma unroll
    for (int i = 0; i < 32; i += 8)
        t[ty + i][tx] = W[(size_t)(k0 + ty + i) * Nd + n0 + tx];
    __syncthreads();
    #pragma unroll
    for (int i = 0; i < 32; i += 8)
        W2[(size_t)(n0 + ty + i) * EMBD + k0 + tx] = __float2half_rn(t[tx][ty + i]);
}

// ---------------------------------------------------------------------------
// fp16 tensor-core GEMM: C[M,N] = A[M,1024] @ W[N,1024]^T + bias
// 128x128 tile, BK=64, 8 warps, 3-stage cp.async pipeline.
// MODE 0: fp32 out.  MODE 1: QKV epilogue scatter into Qp/Kp/Vh head-major.
// ---------------------------------------------------------------------------
#define STAGE_SZ     32768               // A 16KB + B 16KB
#define GEMM_SMEM_SZ (3 * STAGE_SZ)      // 98304

__device__ __forceinline__ void load_stage(uint32_t st,
                                           const __half* A, const __half* B,
                                           int bm, int bn, int kc, int tid)
{
    const size_t ko = (size_t)kc * 64;
    const uint32_t sA = st, sB = st + 16384;
    #pragma unroll
    for (int i = 0; i < 4; i++) {
        const int idx = tid + i * 256;
        const int r = idx >> 3;
        const int g = idx & 7;
        const uint32_t so = (uint32_t)r * 128 + (uint32_t)((g ^ (r & 7)) << 4);
        cp_async16(sA + so, (const char*)(A + (size_t)(bm + r) * EMBD + ko) + g * 16);
        cp_async16(sB + so, (const char*)(B + (size_t)(bn + r) * EMBD + ko) + g * 16);
    }
}

template <int MODE>
__global__ __launch_bounds__(256, 2)
void gemm_fp16(const __half* __restrict__ A2, const __half* __restrict__ W2,
               const float* __restrict__ bias, float* __restrict__ C, int N,
               __half2* __restrict__ Qp, __half2* __restrict__ Kp,
               __half2* __restrict__ Vh)
{
    extern __shared__ char dsm[];
    const int tid  = threadIdx.x;
    const int lane = tid & 31;
    const int wid  = tid >> 5;
    const int wm   = wid >> 2;
    const int wn   = wid & 3;
    const int bm   = blockIdx.y * 128;
    const int bn   = blockIdx.x * 128;

    const uint32_t sbase = smem_u32(dsm);
    float acc[4][4][4];
    #pragma unroll
    for (int mt = 0; mt < 4; mt++)
        #pragma unroll
        for (int nt = 0; nt < 4; nt++)
            #pragma unroll
            for (int j = 0; j < 4; j++) acc[mt][nt][j] = 0.f;

    const int NK = EMBD / 64;   // 16

    load_stage(sbase,            A2, W2, bm, bn, 0, tid);
    cp_commit();
    load_stage(sbase + STAGE_SZ, A2, W2, bm, bn, 1, tid);
    cp_commit();

    uint32_t stage = 0;
    for (int kc = 0; kc < NK; kc++) {
        if (kc == NK - 1) cp_wait<0>(); else cp_wait<1>();
        __syncthreads();
        if (kc + 2 < NK) {
            uint32_t nb = stage + 2;
            if (nb >= 3) nb -= 3;
            load_stage(sbase + nb * STAGE_SZ, A2, W2, bm, bn, kc + 2, tid);
            cp_commit();
        }

        const uint32_t sA = sbase + stage * STAGE_SZ;
        const uint32_t sB = sA + 16384;
        if (++stage == 3) stage = 0;

        #pragma unroll
        for (int ks = 0; ks < 4; ks++) {
            uint32_t a[4][4], bb[2][4];
            #pragma unroll
            for (int mt = 0; mt < 4; mt++) {
                const int r = wm * 64 + mt * 16 + (lane & 15);
                const int g = ks * 2 + (lane >> 4);
                ldmatrix_x4(a[mt], sA + r * 128 + ((g ^ (r & 7)) << 4));
            }
            #pragma unroll
            for (int pp = 0; pp < 2; pp++) {
                const int n = wn * 32 + pp * 16 + ((lane >> 4) << 3) + (lane & 7);
                const int g = ks * 2 + ((lane >> 3) & 1);
                ldmatrix_x4(bb[pp], sB + n * 128 + ((g ^ (n & 7)) << 4));
            }
            #pragma unroll
            for (int mt = 0; mt < 4; mt++) {
                mma16816h(acc[mt][0], a[mt], bb[0] + 0);
                mma16816h(acc[mt][1], a[mt], bb[0] + 2);
                mma16816h(acc[mt][2], a[mt], bb[1] + 0);
                mma16816h(acc[mt][3], a[mt], bb[1] + 2);
            }
        }
    }
    __syncthreads();

    #pragma unroll
    for (int mt = 0; mt < 4; mt++) {
        const int r0 = bm + wm * 64 + mt * 16 + (lane >> 2);
        #pragma unroll
        for (int nt = 0; nt < 4; nt++) {
            const int c0 = bn + wn * 32 + nt * 8 + 2 * (lane & 3);
            const float b0 = bias[c0], b1 = bias[c0 + 1];
            float2 v0 = make_float2(acc[mt][nt][0] + b0, acc[mt][nt][1] + b1);
            float2 v1 = make_float2(acc[mt][nt][2] + b0, acc[mt][nt][3] + b1);
            if (MODE == 0) {
                *(float2*)&C[(size_t)r0 * N + c0]       = v0;
                *(float2*)&C[(size_t)(r0 + 8) * N + c0] = v1;
            } else {
                #pragma unroll
                for (int half_row = 0; half_row < 2; half_row++) {
                    const int row = r0 + half_row * 8;
                    const float2 v = half_row ? v1 : v0;
                    const int bb2 = row >> 11;
                    const int t   = row & 2047;
                    const int reg = c0 >> 10;        // 0=q 1=k 2=v
                    const int cc  = c0 & 1023;
                    const int h   = cc >> 6;
                    const int d2  = (cc & 63) >> 1;
                    const size_t ob = ((size_t)(bb2 * NHEAD + h) * SEQ + t);
                    if (reg == 0) {
                        __half2 H, L;
                        split2h(v.x, v.y, H, L);
                        Qp[ob * 64 + d2]      = H;   // q hi
                        Qp[ob * 64 + 32 + d2] = L;   // q lo (compensation)
                    } else if (reg == 1) {
                        Kp[ob * 32 + d2] = __floats2half2_rn(v.x, v.y);
                    } else {
                        Vh[ob * 32 + d2] = __floats2half2_rn(v.x, v.y);
                    }
                }
            }
        }
    }
}

// ---------------------------------------------------------------------------
// Tensor-core causal flash attention (fp16; Q-side compensation, K stored 1x).
// Block: 128 queries of one (b,h); 8 warps x 16 rows; 64-key tiles.
// SMEM: Q' [128][256B] + K [64][128B] + Vh [64][128B] = 48KB.
// QK: for each k16 slice, S += qh.k + ql.k (2 MMAs reuse one K fragment).
// Epilogue writes fp16 O rows (proj GEMM input) directly.
// ---------------------------------------------------------------------------
#define ATT_SMEM (32768 + 8192 + 8192)   // 49152
#define CEXP 0.18033688f   // 0.125 * log2(e)

__global__ __launch_bounds__(256, 2)
void flash_attn_tc(const __half* __restrict__ Qp, const __half* __restrict__ Kpp,
                   const __half* __restrict__ Vh, __half* __restrict__ a2out)
{
    extern __shared__ char dsm[];
    const uint32_t sQ  = smem_u32(dsm);
    const uint32_t sK  = sQ + 32768;
    const uint32_t sVh = sK + 8192;

    const int qt   = 15 - blockIdx.x;      // heavy tiles first
    const int bh   = blockIdx.y;
    const int b    = bh >> 4;
    const int h    = bh & 15;
    const int tid  = threadIdx.x;
    const int lane = tid & 31;
    const int w    = tid >> 5;
    const int qr0  = qt * 128;

    // ---- load Q' tile (resident): 128 rows x 256B = [qh(64) | ql(64)] ----
    const __half* Qg = Qp + ((size_t)bh * SEQ + qr0) * 128;
    #pragma unroll
    for (int i = 0; i < 8; i++) {
        const int idx = tid + i * 256;     // 0..2047
        const int r = idx >> 4;
        const int g = idx & 15;
        const uint32_t sw = (g & 8) | ((g ^ r) & 7);
        cp_async16(sQ + r * 256 + sw * 16, Qg + (size_t)r * 128 + g * 8);
    }
    cp_commit();
    cp_wait<0>();
    __syncthreads();

    float O[8][4];
    #pragma unroll
    for (int j = 0; j < 8; j++)
        #pragma unroll
        for (int i = 0; i < 4; i++) O[j][i] = 0.f;
    float m0 = -1e30f, m1 = -1e30f, l0 = 0.f, l1 = 0.f;

    const int wrow = qr0 + w * 16;
    const int kt_max_w = (wrow + 15) >> 6;
    const int nkt = 2 * qt + 2;

    const __half* Kg  = Kpp + (size_t)bh * SEQ * 64;
    const __half* VhG = Vh  + (size_t)bh * SEQ * 64;

    for (int kt = 0; kt < nkt; kt++) {
        __syncthreads();
        // ---- load K / Vh tiles (64 rows x 128B each) ----
        {
            const __half* kg  = Kg  + (size_t)(kt * 64) * 64;
            const __half* vhg = VhG + (size_t)(kt * 64) * 64;
            #pragma unroll
            for (int i = 0; i < 2; i++) {
                const int f = tid + i * 256;   // 0..511
                const int r = f >> 3;
                const int g = f & 7;
                const uint32_t sw = (uint32_t)((g ^ (r & 7)) << 4);
                cp_async16(sK  + r * 128 + sw, kg  + (size_t)r * 64 + g * 8);
                cp_async16(sVh + r * 128 + sw, vhg + (size_t)r * 64 + g * 8);
            }
        }
        cp_commit();
        cp_wait<0>();
        __syncthreads();

        if (kt > kt_max_w) continue;

        // ---- S = Qh.K^T + Ql.K^T (Q compensation reusing K fragments) ----
        float S[8][4];
        #pragma unroll
        for (int j = 0; j < 8; j++)
            #pragma unroll
            for (int i = 0; i < 4; i++) S[j][i] = 0.f;

        #pragma unroll
        for (int ks = 0; ks < 4; ks++) {
            uint32_t qfh[4], qfl[4];
            {
                const int r = w * 16 + (lane & 15);
                const int gh = 2 * ks + (lane >> 4);        // hi groups 0..7
                const int gl = gh + 8;                      // lo groups 8..15
                const uint32_t swh = (gh & 8) | ((gh ^ r) & 7);
                const uint32_t swl = (gl & 8) | ((gl ^ r) & 7);
                ldmatrix_x4(qfh, sQ + r * 256 + swh * 16);
                ldmatrix_x4(qfl, sQ + r * 256 + swl * 16);
            }
            #pragma unroll
            for (int nt = 0; nt < 8; nt++) {
                uint32_t kb[2];
                const int n = nt * 8 + (lane & 7);
                const int g = 2 * ks + ((lane >> 3) & 1);
                const uint32_t sw = (g ^ (n & 7));
                ldmatrix_x2(kb, sK + n * 128 + sw * 16);
                mma16816h(S[nt], qfh, kb);
                mma16816h(S[nt], qfl, kb);
            }
        }

        // ---- causal mask ----
        const int r0g = wrow + (lane >> 2);
        const int r1g = r0g + 8;
        if (kt * 64 + 63 > wrow) {
            #pragma unroll
            for (int nt = 0; nt < 8; nt++) {
                const int c = kt * 64 + nt * 8 + 2 * (lane & 3);
                if (c     > r0g) S[nt][0] = -1e30f;
                if (c + 1 > r0g) S[nt][1] = -1e30f;
                if (c     > r1g) S[nt][2] = -1e30f;
                if (c + 1 > r1g) S[nt][3] = -1e30f;
            }
        }

        // ---- online softmax ----
        float mt0 = -1e30f, mt1 = -1e30f;
        #pragma unroll
        for (int nt = 0; nt < 8; nt++) {
            mt0 = fmaxf(mt0, fmaxf(S[nt][0], S[nt][1]));
            mt1 = fmaxf(mt1, fmaxf(S[nt][2], S[nt][3]));
        }
        mt0 = fmaxf(mt0, __shfl_xor_sync(0xffffffffu, mt0, 1));
        mt0 = fmaxf(mt0, __shfl_xor_sync(0xffffffffu, mt0, 2));
        mt1 = fmaxf(mt1, __shfl_xor_sync(0xffffffffu, mt1, 1));
        mt1 = fmaxf(mt1, __shfl_xor_sync(0xffffffffu, mt1, 2));
        const float mn0 = fmaxf(m0, mt0), mn1 = fmaxf(m1, mt1);
        const float c0 = ex2f((m0 - mn0) * CEXP);
        const float c1 = ex2f((m1 - mn1) * CEXP);
        l0 *= c0; l1 *= c1;
        m0 = mn0; m1 = mn1;
        #pragma unroll
        for (int j = 0; j < 8; j++) {
            O[j][0] *= c0; O[j][1] *= c0;
            O[j][2] *= c1; O[j][3] *= c1;
        }
        #pragma unroll
        for (int nt = 0; nt < 8; nt++) {
            S[nt][0] = ex2f((S[nt][0] - mn0) * CEXP);
            S[nt][1] = ex2f((S[nt][1] - mn0) * CEXP);
            S[nt][2] = ex2f((S[nt][2] - mn1) * CEXP);
            S[nt][3] = ex2f((S[nt][3] - mn1) * CEXP);
            l0 += S[nt][0] + S[nt][1];
            l1 += S[nt][2] + S[nt][3];
        }

        // ---- O += P.Vh, P in plain fp16 ----
        #pragma unroll
        for (int ks2 = 0; ks2 < 4; ks2++) {
            uint32_t ap[4];
            __half2 p0 = __floats2half2_rn(S[2*ks2  ][0], S[2*ks2  ][1]);
            __half2 p1 = __floats2half2_rn(S[2*ks2  ][2], S[2*ks2  ][3]);
            __half2 p2 = __floats2half2_rn(S[2*ks2+1][0], S[2*ks2+1][1]);
            __half2 p3 = __floats2half2_rn(S[2*ks2+1][2], S[2*ks2+1][3]);
            ap[0] = *reinterpret_cast<uint32_t*>(&p0);
            ap[1] = *reinterpret_cast<uint32_t*>(&p1);
            ap[2] = *reinterpret_cast<uint32_t*>(&p2);
            ap[3] = *reinterpret_cast<uint32_t*>(&p3);
            #pragma unroll
            for (int np = 0; np < 4; np++) {
                const int r = 16 * ks2 + (lane & 15);
                const int g = 2 * np + (lane >> 4);
                const uint32_t addr_off = r * 128 + (((g ^ (r & 7)) & 7) << 4);
                uint32_t bhv[4];
                ldmatrix_x4t(bhv, sVh + addr_off);
                mma16816h(O[2*np],     ap, bhv + 0);
                mma16816h(O[2*np + 1], ap, bhv + 2);
            }
        }
    }

    // ---- finalize: normalize and write fp16 proj-GEMM input ----
    l0 += __shfl_xor_sync(0xffffffffu, l0, 1);
    l0 += __shfl_xor_sync(0xffffffffu, l0, 2);
    l1 += __shfl_xor_sync(0xffffffffu, l1, 1);
    l1 += __shfl_xor_sync(0xffffffffu, l1, 2);
    const float inv0 = 1.f / l0, inv1 = 1.f / l1;
    const int r0g = wrow + (lane >> 2);
    __half2* a2h = (__half2*)a2out;
    #pragma unroll
    for (int nt = 0; nt < 8; nt++) {
        const int col = h * 64 + nt * 8 + 2 * (lane & 3);
        const size_t row0 = (size_t)(b * SEQ + r0g);
        const size_t row1 = row0 + 8;
        a2h[row0 * 512 + (col >> 1)] = __floats2half2_rn(O[nt][0] * inv0, O[nt][1] * inv0);
        a2h[row1 * 512 + (col >> 1)] = __floats2half2_rn(O[nt][2] * inv1, O[nt][3] * inv1);
    }
}

// ---------------------------------------------------------------------------
// Launch
// ---------------------------------------------------------------------------
extern "C" void kernel_launch(void* const* d_in, const int* in_sizes, int n_in,
                              void* d_out, int out_size)
{
    const float* x      = (const float*)d_in[0];
    const float* W_attn = (const float*)d_in[1];
    const float* b_attn = (const float*)d_in[2];
    const float* W_proj = (const float*)d_in[3];
    const float* b_proj = (const float*)d_in[4];
    float* out = (float*)d_out;

    __half *a2, *w2a, *w2p, *Qp, *Kpq, *Vh;
    cudaGetSymbolAddress((void**)&a2,  g_a2);
    cudaGetSymbolAddress((void**)&w2a, g_w2a);
    cudaGetSymbolAddress((void**)&w2p, g_w2p);
    cudaGetSymbolAddress((void**)&Qp,  g_Qp);
    cudaGetSymbolAddress((void**)&Kpq, g_Kp);
    cudaGetSymbolAddress((void**)&Vh,  g_Vh);

    cudaFuncSetAttribute(gemm_fp16<0>,
                         cudaFuncAttributeMaxDynamicSharedMemorySize, GEMM_SMEM_SZ);
    cudaFuncSetAttribute(gemm_fp16<1>,
                         cudaFuncAttributeMaxDynamicSharedMemorySize, GEMM_SMEM_SZ);
    cudaFuncSetAttribute(flash_attn_tc,
                         cudaFuncAttributeMaxDynamicSharedMemorySize, ATT_SMEM);

    const int n4 = MROWS * EMBD / 4;

    // packs
    pack_half<<<(n4 + 255) / 256, 256>>>(x, a2, n4);
    transpose_pack<<<dim3(QKV_N / 32, EMBD / 32), 256>>>(W_attn, w2a, QKV_N);
    transpose_pack<<<dim3(EMBD / 32,  EMBD / 32), 256>>>(W_proj, w2p, EMBD);

    // 1) QKV projection + fused scatter into attention operands
    gemm_fp16<1><<<dim3(QKV_N / 128, MROWS / 128), 256, GEMM_SMEM_SZ>>>(
        a2, w2a, b_attn, nullptr, QKV_N,
        (__half2*)Qp, (__half2*)Kpq, (__half2*)Vh);

    // 2) tensor-core flash attention, writes fp16 proj input into a2
    flash_attn_tc<<<dim3(16, BATCH * NHEAD), 256, ATT_SMEM>>>(Qp, Kpq, Vh, a2);

    // 3) output projection
    gemm_fp16<0><<<dim3(EMBD / 128, MROWS / 128), 256, GEMM_SMEM_SZ>>>(
        a2, w2p, b_proj, out, EMBD, nullptr, nullptr, nullptr);
}

// round 9
// speedup vs baseline: 8.7277x; 1.0165x over previous
#include <cuda_runtime.h>
#include <cuda_fp16.h>
#include <cstdint>
#include <math.h>

// Problem constants
#define BATCH   4
#define SEQ     2048
#define EMBD    1024
#define NHEAD   16
#define HDIM    64
#define MROWS   (BATCH * SEQ)        // 8192
#define QKV_N   (3 * EMBD)           // 3072

// ---------------------------------------------------------------------------
// Scratch (device globals: allocation-free per harness rules)
// ---------------------------------------------------------------------------
__device__ __half g_a2 [(size_t)MROWS * EMBD];  // [8192,1024] fp16 (x, then attn-out)
__device__ __half g_w2a[(size_t)QKV_N * EMBD];  // [3072,1024] fp16 W_attn^T
__device__ __half g_w2p[(size_t)EMBD * EMBD];   // [1024,1024] fp16 W_proj^T
// attention operands, head-major
__device__ __half g_Qp[(size_t)BATCH * NHEAD * SEQ * 128]; // [qh|ql] (comp kept)
__device__ __half g_Kp[(size_t)BATCH * NHEAD * SEQ * 64];  // kh
__device__ __half g_Vh[(size_t)BATCH * NHEAD * SEQ * 64];  // vh

// ---------------------------------------------------------------------------
// Portable PTX helpers (valid on compute_103)
// ---------------------------------------------------------------------------
__device__ __forceinline__ uint32_t smem_u32(const void* p) {
    uint32_t a;
    asm("{ .reg .u64 t; cvta.to.shared.u64 t, %1; cvt.u32.u64 %0, t; }"
        : "=r"(a) : "l"(p));
    return a;
}
__device__ __forceinline__ void cp_async16(uint32_t dst, const void* src) {
    asm volatile("cp.async.cg.shared.global [%0], [%1], 16;"
                 :: "r"(dst), "l"(src) : "memory");
}
__device__ __forceinline__ void cp_commit() {
    asm volatile("cp.async.commit_group;" ::: "memory");
}
template <int N>
__device__ __forceinline__ void cp_wait() {
    asm volatile("cp.async.wait_group %0;" :: "n"(N) : "memory");
}
__device__ __forceinline__ void ldmatrix_x4(uint32_t* r, uint32_t addr) {
    asm volatile("ldmatrix.sync.aligned.m8n8.x4.shared.b16 {%0,%1,%2,%3}, [%4];"
                 : "=r"(r[0]), "=r"(r[1]), "=r"(r[2]), "=r"(r[3]) : "r"(addr));
}
__device__ __forceinline__ void ldmatrix_x4t(uint32_t* r, uint32_t addr) {
    asm volatile("ldmatrix.sync.aligned.m8n8.x4.trans.shared.b16 {%0,%1,%2,%3}, [%4];"
                 : "=r"(r[0]), "=r"(r[1]), "=r"(r[2]), "=r"(r[3]) : "r"(addr));
}
__device__ __forceinline__ void ldmatrix_x2(uint32_t* r, uint32_t addr) {
    asm volatile("ldmatrix.sync.aligned.m8n8.x2.shared.b16 {%0,%1}, [%2];"
                 : "=r"(r[0]), "=r"(r[1]) : "r"(addr));
}
__device__ __forceinline__ void mma16816h(float* c, const uint32_t* a, const uint32_t* b) {
    asm volatile(
        "mma.sync.aligned.m16n8k16.row.col.f32.f16.f16.f32 "
        "{%0,%1,%2,%3}, {%4,%5,%6,%7}, {%8,%9}, {%0,%1,%2,%3};"
        : "+f"(c[0]), "+f"(c[1]), "+f"(c[2]), "+f"(c[3])
        : "r"(a[0]), "r"(a[1]), "r"(a[2]), "r"(a[3]), "r"(b[0]), "r"(b[1]));
}
__device__ __forceinline__ float ex2f(float x) {
    float r;
    asm("ex2.approx.f32 %0, %1;" : "=f"(r) : "f"(x));
    return r;
}
// split (x,y) into half2 hi + half2 residual
__device__ __forceinline__ void split2h(float x, float y, __half2& H, __half2& L) {
    __half hx = __float2half_rn(x), hy = __float2half_rn(y);
    H = __halves2half2(hx, hy);
    L = __halves2half2(__float2half_rn(x - __half2float(hx)),
                       __float2half_rn(y - __half2float(hy)));
}

// ---------------------------------------------------------------------------
// Pack x fp32 [rows,1024] -> fp16 [rows,1024]
// ---------------------------------------------------------------------------
__global__ __launch_bounds__(256)
void pack_half(const float* __restrict__ src, __half* __restrict__ dst, int n4)
{
    int i = blockIdx.x * 256 + threadIdx.x;
    if (i >= n4) return;
    float4 v = ((const float4*)src)[i];
    __half2* d = (__half2*)dst;
    d[2 * i + 0] = __floats2half2_rn(v.x, v.y);
    d[2 * i + 1] = __floats2half2_rn(v.z, v.w);
}

// ---------------------------------------------------------------------------
// W [K=1024, N] fp32 -> W2 [N, 1024] fp16
// ---------------------------------------------------------------------------
__global__ __launch_bounds__(256)
void transpose_pack(const float* __restrict__ W, __half* __restrict__ W2, int Nd)
{
    __shared__ float t[32][33];
    const int n0 = blockIdx.x * 32;
    const int k0 = blockIdx.y * 32;
    const int tx = threadIdx.x & 31;
    const int ty = threadIdx.x >> 5;
    #pragma unroll
    for (int i = 0; i < 32; i += 8)
        t[ty + i][tx] = W[(size_t)(k0 + ty + i) * Nd + n0 + tx];
    __syncthreads();
    #pragma unroll
    for (int i = 0; i < 32; i += 8)
        W2[(size_t)(n0 + ty + i) * EMBD + k0 + tx] = __float2half_rn(t[tx][ty + i]);
}

// ---------------------------------------------------------------------------
// fp16 tensor-core GEMM: C[M,N] = A[M,1024] @ W[N,1024]^T + bias
// 128x128 tile, BK=64, 8 warps, 3-stage cp.async pipeline.
// MODE 0: fp32 out.  MODE 1: QKV epilogue scatter into Qp/Kp/Vh head-major.
// ---------------------------------------------------------------------------
#define STAGE_SZ     32768               // A 16KB + B 16KB
#define GEMM_SMEM_SZ (3 * STAGE_SZ)      // 98304

__device__ __forceinline__ void load_stage(uint32_t st,
                                           const __half* A, const __half* B,
                                           int bm, int bn, int kc, int tid)
{
    const size_t ko = (size_t)kc * 64;
    const uint32_t sA = st, sB = st + 16384;
    #pragma unroll
    for (int i = 0; i < 4; i++) {
        const int idx = tid + i * 256;
        const int r = idx >> 3;
        const int g = idx & 7;
        const uint32_t so = (uint32_t)r * 128 + (uint32_t)((g ^ (r & 7)) << 4);
        cp_async16(sA + so, (const char*)(A + (size_t)(bm + r) * EMBD + ko) + g * 16);
        cp_async16(sB + so, (const char*)(B + (size_t)(bn + r) * EMBD + ko) + g * 16);
    }
}

template <int MODE>
__global__ __launch_bounds__(256, 2)
void gemm_fp16(const __half* __restrict__ A2, const __half* __restrict__ W2,
               const float* __restrict__ bias, float* __restrict__ C, int N,
               __half2* __restrict__ Qp, __half2* __restrict__ Kp,
               __half2* __restrict__ Vh)
{
    extern __shared__ char dsm[];
    const int tid  = threadIdx.x;
    const int lane = tid & 31;
    const int wid  = tid >> 5;
    const int wm   = wid >> 2;
    const int wn   = wid & 3;
    const int bm   = blockIdx.y * 128;
    const int bn   = blockIdx.x * 128;

    const uint32_t sbase = smem_u32(dsm);
    float acc[4][4][4];
    #pragma unroll
    for (int mt = 0; mt < 4; mt++)
        #pragma unroll
        for (int nt = 0; nt < 4; nt++)
            #pragma unroll
            for (int j = 0; j < 4; j++) acc[mt][nt][j] = 0.f;

    const int NK = EMBD / 64;   // 16

    load_stage(sbase,            A2, W2, bm, bn, 0, tid);
    cp_commit();
    load_stage(sbase + STAGE_SZ, A2, W2, bm, bn, 1, tid);
    cp_commit();

    uint32_t stage = 0;
    for (int kc = 0; kc < NK; kc++) {
        if (kc == NK - 1) cp_wait<0>(); else cp_wait<1>();
        __syncthreads();
        if (kc + 2 < NK) {
            uint32_t nb = stage + 2;
            if (nb >= 3) nb -= 3;
            load_stage(sbase + nb * STAGE_SZ, A2, W2, bm, bn, kc + 2, tid);
            cp_commit();
        }

        const uint32_t sA = sbase + stage * STAGE_SZ;
        const uint32_t sB = sA + 16384;
        if (++stage == 3) stage = 0;

        #pragma unroll
        for (int ks = 0; ks < 4; ks++) {
            uint32_t a[4][4], bb[2][4];
            #pragma unroll
            for (int mt = 0; mt < 4; mt++) {
                const int r = wm * 64 + mt * 16 + (lane & 15);
                const int g = ks * 2 + (lane >> 4);
                ldmatrix_x4(a[mt], sA + r * 128 + ((g ^ (r & 7)) << 4));
            }
            #pragma unroll
            for (int pp = 0; pp < 2; pp++) {
                const int n = wn * 32 + pp * 16 + ((lane >> 4) << 3) + (lane & 7);
                const int g = ks * 2 + ((lane >> 3) & 1);
                ldmatrix_x4(bb[pp], sB + n * 128 + ((g ^ (n & 7)) << 4));
            }
            #pragma unroll
            for (int mt = 0; mt < 4; mt++) {
                mma16816h(acc[mt][0], a[mt], bb[0] + 0);
                mma16816h(acc[mt][1], a[mt], bb[0] + 2);
                mma16816h(acc[mt][2], a[mt], bb[1] + 0);
                mma16816h(acc[mt][3], a[mt], bb[1] + 2);
            }
        }
    }
    __syncthreads();

    #pragma unroll
    for (int mt = 0; mt < 4; mt++) {
        const int r0 = bm + wm * 64 + mt * 16 + (lane >> 2);
        #pragma unroll
        for (int nt = 0; nt < 4; nt++) {
            const int c0 = bn + wn * 32 + nt * 8 + 2 * (lane & 3);
            const float b0 = bias[c0], b1 = bias[c0 + 1];
            float2 v0 = make_float2(acc[mt][nt][0] + b0, acc[mt][nt][1] + b1);
            float2 v1 = make_float2(acc[mt][nt][2] + b0, acc[mt][nt][3] + b1);
            if (MODE == 0) {
                *(float2*)&C[(size_t)r0 * N + c0]       = v0;
                *(float2*)&C[(size_t)(r0 + 8) * N + c0] = v1;
            } else {
                #pragma unroll
                for (int half_row = 0; half_row < 2; half_row++) {
                    const int row = r0 + half_row * 8;
                    const float2 v = half_row ? v1 : v0;
                    const int bb2 = row >> 11;
                    const int t   = row & 2047;
                    const int reg = c0 >> 10;        // 0=q 1=k 2=v
                    const int cc  = c0 & 1023;
                    const int h   = cc >> 6;
                    const int d2  = (cc & 63) >> 1;
                    const size_t ob = ((size_t)(bb2 * NHEAD + h) * SEQ + t);
                    if (reg == 0) {
                        __half2 H, L;
                        split2h(v.x, v.y, H, L);
                        Qp[ob * 64 + d2]      = H;   // q hi
                        Qp[ob * 64 + 32 + d2] = L;   // q lo (compensation)
                    } else if (reg == 1) {
                        Kp[ob * 32 + d2] = __floats2half2_rn(v.x, v.y);
                    } else {
                        Vh[ob * 32 + d2] = __floats2half2_rn(v.x, v.y);
                    }
                }
            }
        }
    }
}

// ---------------------------------------------------------------------------
// Tensor-core causal flash attention (fp16; Q-side compensation, K stored 1x).
// Block: 128 queries of one (b,h); 8 warps x 16 rows; 64-key tiles,
// DOUBLE-BUFFERED via cp.async (prefetch kt+1 while computing kt).
// SMEM: Q' [128][256B] + 2 x (K [64][128B] + Vh [64][128B]) = 64KB.
// Epilogue writes fp16 O rows (proj GEMM input) directly.
// ---------------------------------------------------------------------------
#define KV_STAGE 16384                    // K 8KB + V 8KB
#define ATT_SMEM (32768 + 2 * KV_STAGE)   // 65536
#define CEXP 0.18033688f   // 0.125 * log2(e)

__global__ __launch_bounds__(256, 2)
void flash_attn_tc(const __half* __restrict__ Qp, const __half* __restrict__ Kpp,
                   const __half* __restrict__ Vh, __half* __restrict__ a2out)
{
    extern __shared__ char dsm[];
    const uint32_t sQ  = smem_u32(dsm);
    const uint32_t sKV = sQ + 32768;

    const int qt   = 15 - blockIdx.x;      // heavy tiles first
    const int bh   = blockIdx.y;
    const int b    = bh >> 4;
    const int h    = bh & 15;
    const int tid  = threadIdx.x;
    const int lane = tid & 31;
    const int w    = tid >> 5;
    const int qr0  = qt * 128;

    const __half* Kg  = Kpp + (size_t)bh * SEQ * 64;
    const __half* VhG = Vh  + (size_t)bh * SEQ * 64;

    // ---- load Q' tile (resident): 128 rows x 256B = [qh(64) | ql(64)] ----
    const __half* Qg = Qp + ((size_t)bh * SEQ + qr0) * 128;
    #pragma unroll
    for (int i = 0; i < 8; i++) {
        const int idx = tid + i * 256;     // 0..2047
        const int r = idx >> 4;
        const int g = idx & 15;
        const uint32_t sw = (g & 8) | ((g ^ r) & 7);
        cp_async16(sQ + r * 256 + sw * 16, Qg + (size_t)r * 128 + g * 8);
    }
    cp_commit();

    // KV tile loader: stage s, key tile kt
    auto load_kv = [&](int s, int kt) {
        const __half* kg  = Kg  + (size_t)(kt * 64) * 64;
        const __half* vhg = VhG + (size_t)(kt * 64) * 64;
        const uint32_t sK  = sKV + (uint32_t)s * KV_STAGE;
        const uint32_t sVh = sK + 8192;
        #pragma unroll
        for (int i = 0; i < 2; i++) {
            const int f = tid + i * 256;   // 0..511
            const int r = f >> 3;
            const int g = f & 7;
            const uint32_t sw = (uint32_t)((g ^ (r & 7)) << 4);
            cp_async16(sK  + r * 128 + sw, kg  + (size_t)r * 64 + g * 8);
            cp_async16(sVh + r * 128 + sw, vhg + (size_t)r * 64 + g * 8);
        }
    };

    const int nkt = 2 * qt + 2;

    // prologue: prefetch tile 0 (group also covers trailing Q bytes — fine)
    load_kv(0, 0);
    cp_commit();

    float O[8][4];
    #pragma unroll
    for (int j = 0; j < 8; j++)
        #pragma unroll
        for (int i = 0; i < 4; i++) O[j][i] = 0.f;
    float m0 = -1e30f, m1 = -1e30f, l0 = 0.f, l1 = 0.f;

    const int wrow = qr0 + w * 16;
    const int kt_max_w = (wrow + 15) >> 6;

    for (int kt = 0; kt < nkt; kt++) {
        // prefetch next tile into the other stage, then wait for current
        if (kt + 1 < nkt) {
            load_kv((kt + 1) & 1, kt + 1);
            cp_commit();
            cp_wait<1>();
        } else {
            cp_wait<0>();
        }
        __syncthreads();   // tile kt fully visible to all warps

        if (kt <= kt_max_w) {
            const uint32_t sK  = sKV + (uint32_t)(kt & 1) * KV_STAGE;
            const uint32_t sVh = sK + 8192;

            // ---- S = Qh.K^T + Ql.K^T ----
            float S[8][4];
            #pragma unroll
            for (int j = 0; j < 8; j++)
                #pragma unroll
                for (int i = 0; i < 4; i++) S[j][i] = 0.f;

            #pragma unroll
            for (int ks = 0; ks < 4; ks++) {
                uint32_t qfh[4], qfl[4];
                {
                    const int r = w * 16 + (lane & 15);
                    const int gh = 2 * ks + (lane >> 4);        // hi groups 0..7
                    const int gl = gh + 8;                      // lo groups 8..15
                    const uint32_t swh = (gh & 8) | ((gh ^ r) & 7);
                    const uint32_t swl = (gl & 8) | ((gl ^ r) & 7);
                    ldmatrix_x4(qfh, sQ + r * 256 + swh * 16);
                    ldmatrix_x4(qfl, sQ + r * 256 + swl * 16);
                }
                #pragma unroll
                for (int nt = 0; nt < 8; nt++) {
                    uint32_t kb[2];
                    const int n = nt * 8 + (lane & 7);
                    const int g = 2 * ks + ((lane >> 3) & 1);
                    const uint32_t sw = (g ^ (n & 7));
                    ldmatrix_x2(kb, sK + n * 128 + sw * 16);
                    mma16816h(S[nt], qfh, kb);
                    mma16816h(S[nt], qfl, kb);
                }
            }

            // ---- causal mask ----
            const int r0g = wrow + (lane >> 2);
            const int r1g = r0g + 8;
            if (kt * 64 + 63 > wrow) {
                #pragma unroll
                for (int nt = 0; nt < 8; nt++) {
                    const int c = kt * 64 + nt * 8 + 2 * (lane & 3);
                    if (c     > r0g) S[nt][0] = -1e30f;
                    if (c + 1 > r0g) S[nt][1] = -1e30f;
                    if (c     > r1g) S[nt][2] = -1e30f;
                    if (c + 1 > r1g) S[nt][3] = -1e30f;
                }
            }

            // ---- online softmax ----
            float mt0 = -1e30f, mt1 = -1e30f;
            #pragma unroll
            for (int nt = 0; nt < 8; nt++) {
                mt0 = fmaxf(mt0, fmaxf(S[nt][0], S[nt][1]));
                mt1 = fmaxf(mt1, fmaxf(S[nt][2], S[nt][3]));
            }
            mt0 = fmaxf(mt0, __shfl_xor_sync(0xffffffffu, mt0, 1));
            mt0 = fmaxf(mt0, __shfl_xor_sync(0xffffffffu, mt0, 2));
            mt1 = fmaxf(mt1, __shfl_xor_sync(0xffffffffu, mt1, 1));
            mt1 = fmaxf(mt1, __shfl_xor_sync(0xffffffffu, mt1, 2));
            const float mn0 = fmaxf(m0, mt0), mn1 = fmaxf(m1, mt1);
            const float c0 = ex2f((m0 - mn0) * CEXP);
            const float c1 = ex2f((m1 - mn1) * CEXP);
            l0 *= c0; l1 *= c1;
            m0 = mn0; m1 = mn1;
            #pragma unroll
            for (int j = 0; j < 8; j++) {
                O[j][0] *= c0; O[j][1] *= c0;
                O[j][2] *= c1; O[j][3] *= c1;
            }
            #pragma unroll
            for (int nt = 0; nt < 8; nt++) {
                S[nt][0] = ex2f((S[nt][0] - mn0) * CEXP);
                S[nt][1] = ex2f((S[nt][1] - mn0) * CEXP);
                S[nt][2] = ex2f((S[nt][2] - mn1) * CEXP);
                S[nt][3] = ex2f((S[nt][3] - mn1) * CEXP);
                l0 += S[nt][0] + S[nt][1];
                l1 += S[nt][2] + S[nt][3];
            }

            // ---- O += P.Vh, P in plain fp16 ----
            #pragma unroll
            for (int ks2 = 0; ks2 < 4; ks2++) {
                uint32_t ap[4];
                __half2 p0 = __floats2half2_rn(S[2*ks2  ][0], S[2*ks2  ][1]);
                __half2 p1 = __floats2half2_rn(S[2*ks2  ][2], S[2*ks2  ][3]);
                __half2 p2 = __floats2half2_rn(S[2*ks2+1][0], S[2*ks2+1][1]);
                __half2 p3 = __floats2half2_rn(S[2*ks2+1][2], S[2*ks2+1][3]);
                ap[0] = *reinterpret_cast<uint32_t*>(&p0);
                ap[1] = *reinterpret_cast<uint32_t*>(&p1);
                ap[2] = *reinterpret_cast<uint32_t*>(&p2);
                ap[3] = *reinterpret_cast<uint32_t*>(&p3);
                #pragma unroll
                for (int np = 0; np < 4; np++) {
                    const int r = 16 * ks2 + (lane & 15);
                    const int g = 2 * np + (lane >> 4);
                    const uint32_t addr_off = r * 128 + (((g ^ (r & 7)) & 7) << 4);
                    uint32_t bhv[4];
                    ldmatrix_x4t(bhv, sVh + addr_off);
                    mma16816h(O[2*np],     ap, bhv + 0);
                    mma16816h(O[2*np + 1], ap, bhv + 2);
                }
            }
        }

        __syncthreads();   // all warps done with tile kt before it is overwritten
    }

    // ---- finalize: normalize and write fp16 proj-GEMM input ----
    l0 += __shfl_xor_sync(0xffffffffu, l0, 1);
    l0 += __shfl_xor_sync(0xffffffffu, l0, 2);
    l1 += __shfl_xor_sync(0xffffffffu, l1, 1);
    l1 += __shfl_xor_sync(0xffffffffu, l1, 2);
    const float inv0 = 1.f / l0, inv1 = 1.f / l1;
    const int r0g = wrow + (lane >> 2);
    __half2* a2h = (__half2*)a2out;
    #pragma unroll
    for (int nt = 0; nt < 8; nt++) {
        const int col = h * 64 + nt * 8 + 2 * (lane & 3);
        const size_t row0 = (size_t)(b * SEQ + r0g);
        const size_t row1 = row0 + 8;
        a2h[row0 * 512 + (col >> 1)] = __floats2half2_rn(O[nt][0] * inv0, O[nt][1] * inv0);
        a2h[row1 * 512 + (col >> 1)] = __floats2half2_rn(O[nt][2] * inv1, O[nt][3] * inv1);
    }
}

// ---------------------------------------------------------------------------
// Launch
// ---------------------------------------------------------------------------
extern "C" void kernel_launch(void* const* d_in, const int* in_sizes, int n_in,
                              void* d_out, int out_size)
{
    const float* x      = (const float*)d_in[0];
    const float* W_attn = (const float*)d_in[1];
    const float* b_attn = (const float*)d_in[2];
    const float* W_proj = (const float*)d_in[3];
    const float* b_proj = (const float*)d_in[4];
    float* out = (float*)d_out;

    __half *a2, *w2a, *w2p, *Qp, *Kpq, *Vh;
    cudaGetSymbolAddress((void**)&a2,  g_a2);
    cudaGetSymbolAddress((void**)&w2a, g_w2a);
    cudaGetSymbolAddress((void**)&w2p, g_w2p);
    cudaGetSymbolAddress((void**)&Qp,  g_Qp);
    cudaGetSymbolAddress((void**)&Kpq, g_Kp);
    cudaGetSymbolAddress((void**)&Vh,  g_Vh);

    cudaFuncSetAttribute(gemm_fp16<0>,
                         cudaFuncAttributeMaxDynamicSharedMemorySize, GEMM_SMEM_SZ);
    cudaFuncSetAttribute(gemm_fp16<1>,
                         cudaFuncAttributeMaxDynamicSharedMemorySize, GEMM_SMEM_SZ);
    cudaFuncSetAttribute(flash_attn_tc,
                         cudaFuncAttributeMaxDynamicSharedMemorySize, ATT_SMEM);

    const int n4 = MROWS * EMBD / 4;

    // packs
    pack_half<<<(n4 + 255) / 256, 256>>>(x, a2, n4);
    transpose_pack<<<dim3(QKV_N / 32, EMBD / 32), 256>>>(W_attn, w2a, QKV_N);
    transpose_pack<<<dim3(EMBD / 32,  EMBD / 32), 256>>>(W_proj, w2p, EMBD);

    // 1) QKV projection + fused scatter into attention operands
    gemm_fp16<1><<<dim3(QKV_N / 128, MROWS / 128), 256, GEMM_SMEM_SZ>>>(
        a2, w2a, b_attn, nullptr, QKV_N,
        (__half2*)Qp, (__half2*)Kpq, (__half2*)Vh);

    // 2) tensor-core flash attention, writes fp16 proj input into a2
    flash_attn_tc<<<dim3(16, BATCH * NHEAD), 256, ATT_SMEM>>>(Qp, Kpq, Vh, a2);

    // 3) output projection
    gemm_fp16<0><<<dim3(EMBD / 128, MROWS / 128), 256, GEMM_SMEM_SZ>>>(
        a2, w2p, b_proj, out, EMBD, nullptr, nullptr, nullptr);
}